// round 11
// baseline (speedup 1.0000x reference)
#include <cuda_runtime.h>
#include <cuda_bf16.h>
#include <math.h>
#include <stdint.h>

#define Bv 128
#define Dv 512
#define D2 1024
#define Vv 32000
#define Av 64
#define MAXREC 12
#define KCAP 1664
#define SCALE 0.044194173824159216f
#define NPART (Vv/128)   // 250
#define NCLIN 3072

#define B_CL0 250
#define B_PAL0 274
#define B_MEM0 530
#define NB_PAR 658

typedef __nv_bfloat16 bf16;

__device__ __align__(16) float g_gr[Bv*Dv], g_gi[Bv*Dv];
__device__ __align__(16) float g_qr[Bv*Dv], g_qi[Bv*Dv], g_kr[Bv*Dv], g_ki[Bv*Dv], g_vr[Bv*Dv], g_vi[Bv*Dv];
__device__ float g_ssalv[Bv], g_ssala[Bv];
__device__ __align__(16) float g_vresp[Bv*Dv], g_aresp[Bv*Dv];
__device__ __align__(16) float g_rec[Bv*Dv];
__device__ __align__(16) float g_K[KCAP*Dv], g_Vm[KCAP*Dv];
__device__ float g_kn[KCAP];
__device__ float g_grn[Bv];
__device__ float g_cn[Vv];
__device__ float g_pmin[NPART*Bv];
__device__ int   g_pidx[NPART*Bv];
__device__ float g_vqrows[MAXREC*Bv];

__device__ __align__(16) bf16 g_zh[Bv*D2], g_zl[Bv*D2];
__device__ __align__(16) bf16 g_wh[NCLIN*D2], g_wl[NCLIN*D2];
__device__ __align__(16) bf16 g_cbh[(size_t)Vv*D2], g_cbl[(size_t)Vv*D2];
__device__ __align__(16) bf16 g_dTh[(size_t)Vv*D2], g_dTl[(size_t)Vv*D2];

template<int NT>
__device__ __forceinline__ float blockSum(float v, float* sh) {
    int tid = threadIdx.x;
    #pragma unroll
    for (int o = 16; o > 0; o >>= 1) v += __shfl_down_sync(0xffffffffu, v, o);
    if ((tid & 31) == 0) sh[tid >> 5] = v;
    __syncthreads();
    float r = (tid < (NT/32)) ? sh[tid] : 0.f;
    if (tid < 32) {
        #pragma unroll
        for (int o = 16; o > 0; o >>= 1) r += __shfl_down_sync(0xffffffffu, r, o);
        if (tid == 0) sh[0] = r;
    }
    __syncthreads();
    float out = sh[0];
    __syncthreads();
    return out;
}

template<int NT>
__device__ __forceinline__ float blockMax(float v, float* sh) {
    int tid = threadIdx.x;
    #pragma unroll
    for (int o = 16; o > 0; o >>= 1) v = fmaxf(v, __shfl_down_sync(0xffffffffu, v, o));
    if ((tid & 31) == 0) sh[tid >> 5] = v;
    __syncthreads();
    float r = (tid < (NT/32)) ? sh[tid] : -3.0e38f;
    if (tid < 32) {
        #pragma unroll
        for (int o = 16; o > 0; o >>= 1) r = fmaxf(r, __shfl_down_sync(0xffffffffu, r, o));
        if (tid == 0) sh[0] = r;
    }
    __syncthreads();
    float out = sh[0];
    __syncthreads();
    return out;
}

__device__ __forceinline__ void splitStore(float v, bf16* ph, bf16* pl) {
    bf16 h = __float2bfloat16(v);
    *ph = h;
    *pl = __float2bfloat16(v - __bfloat162float(h));
}

__global__ void k_setup(const int* x, const float* embW, const float* mk, const float* mv,
                        const float* Wqr, const float* Wqi, const float* Wkr,
                        const float* Wki, const float* Wvr, const float* Wvi) {
    __shared__ float sh[8];
    int bid = blockIdx.x, tid = threadIdx.x;
    if (bid < Bv) {
        int i = bid;
        const float* e = embW + (size_t)x[i] * D2;
        float sq = 0.f;
        for (int d = tid; d < Dv; d += 256) {
            float r = e[d], im = e[Dv+d];
            g_gr[i*Dv+d] = r; g_gi[i*Dv+d] = im;
            splitStore(r,  &g_zh[i*D2+d],    &g_zl[i*D2+d]);
            splitStore(im, &g_zh[i*D2+Dv+d], &g_zl[i*D2+Dv+d]);
            sq += r*r;
        }
        float tot = blockSum<256>(sq, sh);
        if (tid == 0) g_grn[i] = 1.f / fmaxf(sqrtf(tot), 1e-12f);
    } else if (bid < 2*Bv) {
        int i = bid - Bv;
        float s = 0.f;
        for (int d = tid; d < Dv; d += 256) {
            float k = mk[i*Dv+d];
            g_K[(1536+i)*Dv+d] = k;
            g_Vm[(1536+i)*Dv+d] = mv[i*Dv+d];
            s += k*k;
        }
        float tot = blockSum<256>(s, sh);
        if (tid == 0) g_kn[1536+i] = 1.f / fmaxf(sqrtf(tot), 1e-12f);
    } else {
        int n = (bid - 2*Bv) * 2 + (tid >> 7);
        int tl = tid & 127;
        int grp = n >> 9, c = n & 511;
        const float *s1, *s2; float sg2;
        switch (grp) {
            case 0: s1=Wqr; s2=Wqi; sg2=-1.f; break;
            case 1: s1=Wqi; s2=Wqr; sg2= 1.f; break;
            case 2: s1=Wkr; s2=Wki; sg2=-1.f; break;
            case 3: s1=Wki; s2=Wkr; sg2= 1.f; break;
            case 4: s1=Wvr; s2=Wvi; sg2=-1.f; break;
            default:s1=Wvi; s2=Wvr; sg2= 1.f; break;
        }
        for (int k = tl; k < Dv; k += 128) {
            float v1 = s1[c*Dv + k];
            float v2 = sg2 * s2[c*Dv + k];
            splitStore(v1, &g_wh[n*D2+k],    &g_wl[n*D2+k]);
            splitStore(v2, &g_wh[n*D2+Dv+k], &g_wl[n*D2+Dv+k]);
        }
    }
}

__global__ void k_prep_cb(const float* cb) {
    __shared__ float sh[8];
    int j = blockIdx.x;
    const float* c = cb + (size_t)j * D2;
    float s = 0.f;
    for (int k = threadIdx.x; k < D2; k += 128) {
        float v = c[k];
        s += v*v;
        splitStore(v, &g_cbh[(size_t)j*D2+k], &g_cbl[(size_t)j*D2+k]);
    }
    float tot = blockSum<128>(s, sh);
    if (threadIdx.x == 0) g_cn[j] = tot;
}

__global__ void k_prep_dec(const float* W) {
    __shared__ float tile[32][33];
    int n0 = blockIdx.x * 32, k0 = blockIdx.y * 32;
    int tx = threadIdx.x & 31, ty = threadIdx.x >> 5;
    for (int r = ty; r < 32; r += 8)
        tile[r][tx] = W[(size_t)(k0+r)*Vv + n0 + tx];
    __syncthreads();
    for (int r = ty; r < 32; r += 8) {
        float v = tile[tx][r];
        size_t o = (size_t)(n0+r)*D2 + k0 + tx;
        splitStore(v, &g_dTh[o], &g_dTl[o]);
    }
}

#define MMA16816(c, a, b) \
    asm volatile("mma.sync.aligned.m16n8k16.row.col.f32.bf16.bf16.f32 " \
        "{%0,%1,%2,%3},{%4,%5,%6,%7},{%8,%9},{%0,%1,%2,%3};" \
        : "+f"(c[0]), "+f"(c[1]), "+f"(c[2]), "+f"(c[3]) \
        : "r"(a[0]), "r"(a[1]), "r"(a[2]), "r"(a[3]), "r"(b[0]), "r"(b[1]))

#define LDSM4(d0, d1, d2, d3, addr) \
    asm volatile("ldmatrix.sync.aligned.m8n8.x4.shared.b16 {%0,%1,%2,%3}, [%4];" \
        : "=r"(d0), "=r"(d1), "=r"(d2), "=r"(d3) : "r"(addr))

#define CPA16(dst, src) \
    asm volatile("cp.async.cg.shared.global [%0], [%1], 16;" :: "r"(dst), "l"(src))

__device__ __forceinline__ void updMin(float v, int ix, float& bv, int& bi) {
    if (v < bv || (v == bv && ix < bi)) { bv = v; bi = ix; }
}

#define TP 40
#define SARR (128*TP*2)
#define SSTG (4*SARR)
#define SMEM_MMA (2*SSTG)

template<bool VQMODE>
__device__ __forceinline__ void mma_tile(char* dsm, int n0,
                                         const bf16* __restrict__ Bhp,
                                         const bf16* __restrict__ Blp) {
    const uint32_t sb = (uint32_t)__cvta_generic_to_shared(dsm);
    const int tid = threadIdx.x;
    const int wid = tid >> 5, lane = tid & 31;
    const int wm = wid >> 2, wn = wid & 3;
    const int g = lane >> 2, tig = lane & 3;
    const int tg = lane >> 3, tr = lane & 7;
    const int a_row = ((tg & 1) << 3) + tr;
    const int a_col = (tg >> 1) << 3;
    const int b_row = ((tg >> 1) << 3) + tr;
    const int b_col = (tg & 1) << 3;

    float acc[4][4][4];
    #pragma unroll
    for (int a = 0; a < 4; a++)
        #pragma unroll
        for (int b = 0; b < 4; b++)
            #pragma unroll
            for (int c = 0; c < 4; c++) acc[a][b][c] = 0.f;

    const int zr0 = tid >> 2,         zs0 = (tid & 3) * 8;
    const int zr1 = (tid + 256) >> 2, zs1 = ((tid + 256) & 3) * 8;

    auto loadStage = [&](int stg, int k0) {
        uint32_t s0 = sb + stg * SSTG;
        CPA16(s0 +            (zr0*TP + zs0)*2, &g_zh[(size_t)zr0*D2 + k0 + zs0]);
        CPA16(s0 +            (zr1*TP + zs1)*2, &g_zh[(size_t)zr1*D2 + k0 + zs1]);
        CPA16(s0 +   SARR +   (zr0*TP + zs0)*2, &g_zl[(size_t)zr0*D2 + k0 + zs0]);
        CPA16(s0 +   SARR +   (zr1*TP + zs1)*2, &g_zl[(size_t)zr1*D2 + k0 + zs1]);
        CPA16(s0 + 2*SARR +   (zr0*TP + zs0)*2, &Bhp[(size_t)(n0+zr0)*D2 + k0 + zs0]);
        CPA16(s0 + 2*SARR +   (zr1*TP + zs1)*2, &Bhp[(size_t)(n0+zr1)*D2 + k0 + zs1]);
        CPA16(s0 + 3*SARR +   (zr0*TP + zs0)*2, &Blp[(size_t)(n0+zr0)*D2 + k0 + zs0]);
        CPA16(s0 + 3*SARR +   (zr1*TP + zs1)*2, &Blp[(size_t)(n0+zr1)*D2 + k0 + zs1]);
        asm volatile("cp.async.commit_group;");
    };

    loadStage(0, 0);

    const int NKC = D2 / 32;
    for (int kc = 0; kc < NKC; kc++) {
        if (kc + 1 < NKC) {
            loadStage((kc + 1) & 1, (kc + 1) * 32);
            asm volatile("cp.async.wait_group 1;");
        } else {
            asm volatile("cp.async.wait_group 0;");
        }
        __syncthreads();

        const uint32_t s0 = sb + (kc & 1) * SSTG;
        #pragma unroll
        for (int sub = 0; sub < 2; sub++) {
            const int kb = sub * 16;
            uint32_t af[4][4], bh2[4][2], bl2[4][2];
            #pragma unroll
            for (int fm = 0; fm < 4; fm++) {
                uint32_t addr = s0 + ((wm*64 + fm*16 + a_row)*TP + kb + a_col)*2;
                LDSM4(af[fm][0], af[fm][1], af[fm][2], af[fm][3], addr);
            }
            #pragma unroll
            for (int p = 0; p < 2; p++) {
                uint32_t addr = s0 + 2*SARR + ((wn*32 + p*16 + b_row)*TP + kb + b_col)*2;
                LDSM4(bh2[2*p][0], bh2[2*p][1], bh2[2*p+1][0], bh2[2*p+1][1], addr);
            }
            #pragma unroll
            for (int fm = 0; fm < 4; fm++)
                #pragma unroll
                for (int fn = 0; fn < 4; fn++) MMA16816(acc[fm][fn], af[fm], bh2[fn]);
            #pragma unroll
            for (int p = 0; p < 2; p++) {
                uint32_t addr = s0 + 3*SARR + ((wn*32 + p*16 + b_row)*TP + kb + b_col)*2;
                LDSM4(bl2[2*p][0], bl2[2*p][1], bl2[2*p+1][0], bl2[2*p+1][1], addr);
            }
            #pragma unroll
            for (int fm = 0; fm < 4; fm++)
                #pragma unroll
                for (int fn = 0; fn < 4; fn++) MMA16816(acc[fm][fn], af[fm], bl2[fn]);
            #pragma unroll
            for (int fm = 0; fm < 4; fm++) {
                uint32_t addr = s0 + SARR + ((wm*64 + fm*16 + a_row)*TP + kb + a_col)*2;
                LDSM4(af[fm][0], af[fm][1], af[fm][2], af[fm][3], addr);
            }
            #pragma unroll
            for (int fm = 0; fm < 4; fm++)
                #pragma unroll
                for (int fn = 0; fn < 4; fn++) MMA16816(acc[fm][fn], af[fm], bh2[fn]);
        }
        __syncthreads();
    }

    if (!VQMODE) {
        float* outs[6] = {g_qr, g_qi, g_kr, g_ki, g_vr, g_vi};
        #pragma unroll
        for (int fm = 0; fm < 4; fm++) {
            int r = wm*64 + fm*16 + g;
            #pragma unroll
            for (int fn = 0; fn < 4; fn++) {
                int gcol = n0 + wn*32 + fn*8 + tig*2;
                float* dst = outs[gcol >> 9];
                int c = gcol & 511;
                *(float2*)&dst[r*Dv + c]     = make_float2(acc[fm][fn][0], acc[fm][fn][1]);
                *(float2*)&dst[(r+8)*Dv + c] = make_float2(acc[fm][fn][2], acc[fm][fn][3]);
            }
        }
    } else {
        float* minv = (float*)dsm;
        int*   mini = (int*)(dsm + 128*4*sizeof(float));
        #pragma unroll
        for (int fm = 0; fm < 4; fm++) {
            int r0 = wm*64 + fm*16 + g;
            float bv0 = 3.0e38f, bv1 = 3.0e38f;
            int bi0 = 0x7fffffff, bi1 = 0x7fffffff;
            #pragma unroll
            for (int fn = 0; fn < 4; fn++) {
                int gcol = n0 + wn*32 + fn*8 + tig*2;
                float cn0 = g_cn[gcol], cn1 = g_cn[gcol+1];
                updMin(cn0 - 2.f*acc[fm][fn][0], gcol,   bv0, bi0);
                updMin(cn1 - 2.f*acc[fm][fn][1], gcol+1, bv0, bi0);
                updMin(cn0 - 2.f*acc[fm][fn][2], gcol,   bv1, bi1);
                updMin(cn1 - 2.f*acc[fm][fn][3], gcol+1, bv1, bi1);
            }
            #pragma unroll
            for (int o = 1; o <= 2; o <<= 1) {
                float ov = __shfl_xor_sync(0xffffffffu, bv0, o);
                int   oi = __shfl_xor_sync(0xffffffffu, bi0, o);
                updMin(ov, oi, bv0, bi0);
                ov = __shfl_xor_sync(0xffffffffu, bv1, o);
                oi = __shfl_xor_sync(0xffffffffu, bi1, o);
                updMin(ov, oi, bv1, bi1);
            }
            if (tig == 0) {
                minv[r0*4 + wn] = bv0; mini[r0*4 + wn] = bi0;
                minv[(r0+8)*4 + wn] = bv1; mini[(r0+8)*4 + wn] = bi1;
            }
        }
        __syncthreads();
        if (tid < 128) {
            float bv = 3.0e38f; int bi = 0x7fffffff;
            #pragma unroll
            for (int w = 0; w < 4; w++) updMin(minv[tid*4+w], mini[tid*4+w], bv, bi);
            g_pmin[blockIdx.x*Bv + tid] = bv;
            g_pidx[blockIdx.x*Bv + tid] = bi;
        }
    }
}

__global__ __launch_bounds__(256, 2) void k_par(int off, int M,
                                                const float* __restrict__ vis,
                                                const float* __restrict__ aud,
                                                const float* __restrict__ sw) {
    extern __shared__ __align__(16) char dsm[];
    int bid = blockIdx.x, tid = threadIdx.x;

    if (bid < B_CL0) {
        mma_tile<true>(dsm, bid * 128, g_cbh, g_cbl);
    } else if (bid < B_PAL0) {
        mma_tile<false>(dsm, (bid - B_CL0) * 128, g_wh, g_wl);
    } else if (bid < B_MEM0) {
        __shared__ float pg[Dv];
        __shared__ float plg[Av];
        __shared__ float psh[8];
        int r = bid - B_PAL0;
        int i = r >> 1, z = r & 1;
        const float* src = z ? g_gi : g_gr;
        const float* P   = z ? aud : vis;
        float* resp      = z ? g_aresp : g_vresp;
        const float* swp = sw + z*Dv;
        for (int k = tid; k < Dv; k += 256) pg[k] = src[i*Dv+k];
        __syncthreads();
        {
            int a = tid >> 2, part = tid & 3;
            float s = 0.f;
            const float* pr = &P[a*Dv + part*128];
            const float* gq = &pg[part*128];
            for (int k = 0; k < 128; k += 4) {
                float4 p4 = *(const float4*)&pr[k];
                s += gq[k]*p4.x + gq[k+1]*p4.y + gq[k+2]*p4.z + gq[k+3]*p4.w;
            }
            s += __shfl_xor_sync(0xffffffffu, s, 1);
            s += __shfl_xor_sync(0xffffffffu, s, 2);
            if (part == 0) plg[a] = s;
        }
        __syncthreads();
        if (tid == 0) {
            float mx = -3.0e38f;
            for (int a = 0; a < Av; a++) mx = fmaxf(mx, plg[a]);
            float su = 0.f;
            for (int a = 0; a < Av; a++) { float e = expf(plg[a]-mx); plg[a] = e; su += e; }
            float inv = 1.f/su;
            for (int a = 0; a < Av; a++) plg[a] *= inv;
        }
        __syncthreads();
        float sal = 0.f;
        for (int d = tid; d < Dv; d += 256) {
            float acc = 0.f;
            for (int a = 0; a < Av; a++) acc += plg[a] * P[a*Dv + d];
            resp[i*Dv + d] = acc;
            sal += acc * swp[d];
        }
        float st = blockSum<256>(sal, psh);
        if (tid == 0) { if (z) g_ssala[i] = st; else g_ssalv[i] = st; }
    } else {
        __shared__ float mg[Dv];
        __shared__ float mlg[1536];
        __shared__ float msh[8];
        int i = bid - B_MEM0;
        for (int k = tid; k < Dv; k += 256) mg[k] = g_gr[i*Dv+k];
        __syncthreads();
        float rni = g_grn[i];
        float lmax = -3.0e38f;
        for (int m = tid; m < M; m += 256) {
            const float* kp = &g_K[(size_t)(off+m)*Dv];
            float s0 = 0.f, s1 = 0.f, s2 = 0.f, s3 = 0.f;
            for (int k = 0; k < Dv; k += 16) {
                float4 a = *(const float4*)&kp[k];
                float4 b = *(const float4*)&kp[k+4];
                float4 c = *(const float4*)&kp[k+8];
                float4 d = *(const float4*)&kp[k+12];
                s0 += mg[k]*a.x + mg[k+1]*a.y + mg[k+2]*a.z + mg[k+3]*a.w;
                s1 += mg[k+4]*b.x + mg[k+5]*b.y + mg[k+6]*b.z + mg[k+7]*b.w;
                s2 += mg[k+8]*c.x + mg[k+9]*c.y + mg[k+10]*c.z + mg[k+11]*c.w;
                s3 += mg[k+12]*d.x + mg[k+13]*d.y + mg[k+14]*d.z + mg[k+15]*d.w;
            }
            float l = 5.f * ((s0+s1)+(s2+s3)) * rni * g_kn[off+m];
            mlg[m] = l;
            lmax = fmaxf(lmax, l);
        }
        float mx = blockMax<256>(lmax, msh);
        float lsum = 0.f;
        for (int m = tid; m < M; m += 256) { float e = expf(mlg[m]-mx); mlg[m] = e; lsum += e; }
        float sum = blockSum<256>(lsum, msh);
        float inv = 1.f / sum;
        float a00 = 0.f, a01 = 0.f, a10 = 0.f, a11 = 0.f;
        int m = 0;
        for (; m + 1 < M; m += 2) {
            float w0 = mlg[m], w1 = mlg[m+1];
            const float* vp0 = &g_Vm[(size_t)(off+m)*Dv];
            const float* vp1 = vp0 + Dv;
            a00 += w0 * vp0[tid]; a01 += w0 * vp0[tid+256];
            a10 += w1 * vp1[tid]; a11 += w1 * vp1[tid+256];
        }
        if (m < M) {
            float w0 = mlg[m];
            const float* vp0 = &g_Vm[(size_t)(off+m)*Dv];
            a00 += w0 * vp0[tid]; a01 += w0 * vp0[tid+256];
        }
        g_rec[i*Dv + tid]       = (a00 + a10) * inv;
        g_rec[i*Dv + tid + 256] = (a01 + a11) * inv;
        {
            int noff = off - 128;
            float v0 = mg[tid], v1 = mg[tid + 256];
            g_K [(size_t)(noff+i)*Dv + tid]       = v0;
            g_K [(size_t)(noff+i)*Dv + tid + 256] = v1;
            g_Vm[(size_t)(noff+i)*Dv + tid]       = v0;
            g_Vm[(size_t)(noff+i)*Dv + tid + 256] = v1;
            if (tid == 0) g_kn[noff+i] = rni;
        }
    }
}

__global__ __launch_bounds__(256, 2) void k_dec(const float* __restrict__ bias,
                                                float* __restrict__ out) {
    extern __shared__ __align__(16) char dsm[];
    const uint32_t sb = (uint32_t)__cvta_generic_to_shared(dsm);
    const int tid = threadIdx.x;
    const int wid = tid >> 5, lane = tid & 31;
    const int wm = wid >> 2, wn = wid & 3;
    const int g = lane >> 2, tig = lane & 3;
    const int n0 = blockIdx.x * 128;
    const int tg = lane >> 3, tr = lane & 7;
    const int a_row = ((tg & 1) << 3) + tr;
    const int a_col = (tg >> 1) << 3;
    const int b_row = ((tg >> 1) << 3) + tr;
    const int b_col = (tg & 1) << 3;

    float acc[4][4][4];
    #pragma unroll
    for (int a = 0; a < 4; a++)
        #pragma unroll
        for (int b = 0; b < 4; b++)
            #pragma unroll
            for (int c = 0; c < 4; c++) acc[a][b][c] = 0.f;

    const int zr0 = tid >> 2,         zs0 = (tid & 3) * 8;
    const int zr1 = (tid + 256) >> 2, zs1 = ((tid + 256) & 3) * 8;

    auto loadStage = [&](int stg, int k0) {
        uint32_t s0 = sb + stg * SSTG;
        CPA16(s0 +            (zr0*TP + zs0)*2, &g_zh[(size_t)zr0*D2 + k0 + zs0]);
        CPA16(s0 +            (zr1*TP + zs1)*2, &g_zh[(size_t)zr1*D2 + k0 + zs1]);
        CPA16(s0 +   SARR +   (zr0*TP + zs0)*2, &g_zl[(size_t)zr0*D2 + k0 + zs0]);
        CPA16(s0 +   SARR +   (zr1*TP + zs1)*2, &g_zl[(size_t)zr1*D2 + k0 + zs1]);
        CPA16(s0 + 2*SARR +   (zr0*TP + zs0)*2, &g_dTh[(size_t)(n0+zr0)*D2 + k0 + zs0]);
        CPA16(s0 + 2*SARR +   (zr1*TP + zs1)*2, &g_dTh[(size_t)(n0+zr1)*D2 + k0 + zs1]);
        CPA16(s0 + 3*SARR +   (zr0*TP + zs0)*2, &g_dTl[(size_t)(n0+zr0)*D2 + k0 + zs0]);
        CPA16(s0 + 3*SARR +   (zr1*TP + zs1)*2, &g_dTl[(size_t)(n0+zr1)*D2 + k0 + zs1]);
        asm volatile("cp.async.commit_group;");
    };

    loadStage(0, 0);
    const int NKC = D2 / 32;
    for (int kc = 0; kc < NKC; kc++) {
        if (kc + 1 < NKC) {
            loadStage((kc + 1) & 1, (kc + 1) * 32);
            asm volatile("cp.async.wait_group 1;");
        } else {
            asm volatile("cp.async.wait_group 0;");
        }
        __syncthreads();
        const uint32_t s0 = sb + (kc & 1) * SSTG;
        #pragma unroll
        for (int sub = 0; sub < 2; sub++) {
            const int kb = sub * 16;
            uint32_t af[4][4], bh2[4][2], bl2[4][2];
            #pragma unroll
            for (int fm = 0; fm < 4; fm++) {
                uint32_t addr = s0 + ((wm*64 + fm*16 + a_row)*TP + kb + a_col)*2;
                LDSM4(af[fm][0], af[fm][1], af[fm][2], af[fm][3], addr);
            }
            #pragma unroll
            for (int p = 0; p < 2; p++) {
                uint32_t addr = s0 + 2*SARR + ((wn*32 + p*16 + b_row)*TP + kb + b_col)*2;
                LDSM4(bh2[2*p][0], bh2[2*p][1], bh2[2*p+1][0], bh2[2*p+1][1], addr);
            }
            #pragma unroll
            for (int fm = 0; fm < 4; fm++)
                #pragma unroll
                for (int fn = 0; fn < 4; fn++) MMA16816(acc[fm][fn], af[fm], bh2[fn]);
            #pragma unroll
            for (int p = 0; p < 2; p++) {
                uint32_t addr = s0 + 3*SARR + ((wn*32 + p*16 + b_row)*TP + kb + b_col)*2;
                LDSM4(bl2[2*p][0], bl2[2*p][1], bl2[2*p+1][0], bl2[2*p+1][1], addr);
            }
            #pragma unroll
            for (int fm = 0; fm < 4; fm++)
                #pragma unroll
                for (int fn = 0; fn < 4; fn++) MMA16816(acc[fm][fn], af[fm], bl2[fn]);
            #pragma unroll
            for (int fm = 0; fm < 4; fm++) {
                uint32_t addr = s0 + SARR + ((wm*64 + fm*16 + a_row)*TP + kb + a_col)*2;
                LDSM4(af[fm][0], af[fm][1], af[fm][2], af[fm][3], addr);
            }
            #pragma unroll
            for (int fm = 0; fm < 4; fm++)
                #pragma unroll
                for (int fn = 0; fn < 4; fn++) MMA16816(acc[fm][fn], af[fm], bh2[fn]);
        }
        __syncthreads();
    }
    #pragma unroll
    for (int fm = 0; fm < 4; fm++) {
        int r = wm*64 + fm*16 + g;
        #pragma unroll
        for (int fn = 0; fn < 4; fn++) {
            int gcol = n0 + wn*32 + fn*8 + tig*2;
            float b0 = bias[gcol], b1 = bias[gcol+1];
            *(float2*)&out[(size_t)r*Vv + gcol] =
                make_float2(acc[fm][fn][0] + b0, acc[fm][fn][1] + b1);
            *(float2*)&out[(size_t)(r+8)*Vv + gcol] =
                make_float2(acc[fm][fn][2] + b0, acc[fm][fn][3] + b1);
        }
    }
}

// ===== fused per-row kernel, 512 threads: argmin + attention + LN + salience + combine =====
__global__ __launch_bounds__(512) void k_row(const float* lng, const float* lnb,
        const float* pw, const float* pb, const float* cb, const float* sensb,
        const float* memw, const float* memb, const float* semw, const float* semb, int t) {
    __shared__ float q[D2];
    __shared__ float part[4][Bv];
    __shared__ float att[Bv];
    __shared__ float sh[16];
    __shared__ float w[4];
    __shared__ float sv[512]; __shared__ int si[512];
    int i = blockIdx.x, tid = threadIdx.x;

    {
        float bv = 3.0e38f; int bi = 0x7fffffff;
        if (tid < NPART) { bv = g_pmin[tid*Bv + i]; bi = g_pidx[tid*Bv + i]; }
        sv[tid] = bv; si[tid] = bi;
    }
    q[tid]      = g_qr[i*Dv + tid];
    q[Dv + tid] = g_qi[i*Dv + tid];
    __syncthreads();
    for (int s = 256; s > 0; s >>= 1) {
        if (tid < s) {
            float v = sv[tid+s]; int ix = si[tid+s];
            if (v < sv[tid] || (v == sv[tid] && ix < si[tid])) { sv[tid] = v; si[tid] = ix; }
        }
        __syncthreads();
    }
    int idx = si[0];
    const float* c = &cb[(size_t)idx*D2];

    // logits: 4 threads per key, each handles 256 of the 1024 concat dims
    {
        int j = tid & 127, seg = tid >> 7;           // seg 0..3
        const float* kv = (seg < 2) ? &g_kr[j*Dv + (seg & 1)*256]
                                    : &g_ki[j*Dv + (seg & 1)*256];
        const float* qv = &q[seg*256];
        float s0 = 0.f, s1 = 0.f;
        for (int k = 0; k < 256; k += 8) {
            float4 a = *(const float4*)&kv[k];
            float4 a2 = *(const float4*)&kv[k+4];
            s0 += qv[k]*a.x + qv[k+1]*a.y + qv[k+2]*a.z + qv[k+3]*a.w;
            s1 += qv[k+4]*a2.x + qv[k+5]*a2.y + qv[k+6]*a2.z + qv[k+7]*a2.w;
        }
        part[seg][j] = s0 + s1;
    }
    __syncthreads();
    float logit = (tid < 128)
        ? (part[0][tid] + part[1][tid] + part[2][tid] + part[3][tid]) * SCALE
        : -3.0e38f;
    float mx = blockMax<512>(logit, sh);
    float e = (tid < 128) ? expf(logit - mx) : 0.f;
    float es = blockSum<512>(e, sh);
    if (tid < 128) att[tid] = e / es;
    __syncthreads();

    // attn @ [vr|vi] — thread owns dim d = tid in both real and imag
    float fr = 0.f, fi = 0.f;
    {
        const float* vr = &g_vr[tid];
        const float* vi = &g_vi[tid];
        int j = 0;
        for (; j + 4 <= Bv; j += 4) {
            float w0 = att[j], w1 = att[j+1], w2 = att[j+2], w3 = att[j+3];
            fr += w0*vr[(j)*Dv] + w1*vr[(j+1)*Dv] + w2*vr[(j+2)*Dv] + w3*vr[(j+3)*Dv];
            fi += w0*vi[(j)*Dv] + w1*vi[(j+1)*Dv] + w2*vi[(j+2)*Dv] + w3*vi[(j+3)*Dv];
        }
    }
    float m = blockSum<512>(fr + fi, sh) * (1.f/1024.f);
    float d0 = fr - m, d1 = fi - m;
    float var = blockSum<512>(d0*d0 + d1*d1, sh) * (1.f/1024.f);
    float rstd = rsqrtf(var + 1e-5f);
    int c0 = tid, c2 = Dv + tid;
    float yr = d0*rstd*lng[c0] + lnb[c0];
    float yi = d1*rstd*lng[c2] + lnb[c2];
    float pacc = yr*pw[c0] + yi*pw[c2];
    float psal = blockSum<512>(pacc, sh);

    float recv = g_rec[i*Dv + tid];
    float md = recv * memw[tid];
    float mds = blockSum<512>(md, sh);
    float sd = c[c0]*semw[c0] + c[c2]*semw[c2];
    float sds = blockSum<512>(sd, sh);
    if (tid == 0) {
        float a0 = (psal + pb[0]) * 1.25f;
        float a1 = (g_ssalv[i] + g_ssala[i] + sensb[0]) * 1.25f;
        float a2 = (mds + memb[0]) * 1.25f;
        float a3 = (sds + semb[0]) * 1.25f;
        float mxx = fmaxf(fmaxf(a0,a1), fmaxf(a2,a3));
        float e0 = expf(a0-mxx), e1 = expf(a1-mxx), e2 = expf(a2-mxx), e3 = expf(a3-mxx);
        float inv = 1.f / (e0+e1+e2+e3);
        w[0]=e0*inv; w[1]=e1*inv; w[2]=e2*inv; w[3]=e3*inv;
    }
    __syncthreads();
    float w0 = w[0], w1 = w[1], w2 = w[2], w3 = w[3];
    int d = tid;
    float ogr = g_gr[i*Dv+d], ogi = g_gi[i*Dv+d];
    float cr = c[d], ci = c[Dv+d];
    float dr = cr-ogr, di = ci-ogi;
    float vql = dr*dr + di*di;
    float nr = w0*yr + w1*g_vresp[i*Dv+d] + w2*recv + w3*cr;
    float ni = w0*yi + w1*g_aresp[i*Dv+d]           + w3*ci;
    float ngr = 0.6f*ogr + 0.4f*nr, ngi = 0.6f*ogi + 0.4f*ni;
    g_gr[i*Dv+d] = ngr; g_gi[i*Dv+d] = ngi;
    float sq = ngr*ngr;
    splitStore(ngr, &g_zh[i*D2+d],    &g_zl[i*D2+d]);
    splitStore(ngi, &g_zh[i*D2+Dv+d], &g_zl[i*D2+Dv+d]);
    float sqt = blockSum<512>(sq, sh);
    float vqt = blockSum<512>(vql, sh);
    if (tid == 0) {
        g_grn[i] = 1.f / fmaxf(sqrtf(sqt), 1e-12f);
        g_vqrows[t*Bv + i] = vqt;
    }
}

__global__ void k_fin(float* out) {
    __shared__ float sh[8];
    int tid = threadIdx.x;
    float s = 0.f;
    for (int k = tid; k < MAXREC*Bv; k += 256) s += g_vqrows[k];
    float tot = blockSum<256>(s, sh);
    if (tid == 0) {
        out[(size_t)Bv*Vv]     = 1.25f * tot / 131072.f;
        out[(size_t)Bv*Vv + 1] = (float)MAXREC;
    }
}

extern "C" void kernel_launch(void* const* d_in, const int* in_sizes, int n_in,
                              void* d_out, int out_size) {
    const int*   x    = (const int*)d_in[0];
    const float* embW = (const float*)d_in[1];
    const float* Wqr  = (const float*)d_in[2];
    const float* Wqi  = (const float*)d_in[3];
    const float* Wkr  = (const float*)d_in[4];
    const float* Wki  = (const float*)d_in[5];
    const float* Wvr  = (const float*)d_in[6];
    const float* Wvi  = (const float*)d_in[7];
    const float* lng  = (const float*)d_in[8];
    const float* lnb  = (const float*)d_in[9];
    const float* pw   = (const float*)d_in[10];
    const float* pb   = (const float*)d_in[11];
    const float* vis  = (const float*)d_in[12];
    const float* aud  = (const float*)d_in[13];
    const float* sw   = (const float*)d_in[14];
    const float* sb   = (const float*)d_in[15];
    const float* mk   = (const float*)d_in[16];
    const float* mv   = (const float*)d_in[17];
    const float* memw = (const float*)d_in[18];
    const float* memb = (const float*)d_in[19];
    const float* cb   = (const float*)d_in[20];
    const float* semw = (const float*)d_in[21];
    const float* semb = (const float*)d_in[22];
    const float* decW = (const float*)d_in[23];
    const float* decb = (const float*)d_in[24];
    float* out = (float*)d_out;

    cudaFuncSetAttribute(k_par, cudaFuncAttributeMaxDynamicSharedMemorySize, SMEM_MMA);
    cudaFuncSetAttribute(k_dec, cudaFuncAttributeMaxDynamicSharedMemorySize, SMEM_MMA);

    k_setup<<<2*Bv + NCLIN/2, 256>>>(x, embW, mk, mv, Wqr, Wqi, Wkr, Wki, Wvr, Wvi); // 0
    k_prep_cb<<<Vv, 128>>>(cb);                                                       // 1

    for (int t = 0; t < MAXREC; t++) {
        int off = 1536 - 128*t;
        int M   = 128 + 127*t;
        k_par<<<NB_PAR, 256, SMEM_MMA>>>(off, M, vis, aud, sw);                       // 2 on t==0
        k_row<<<Bv, 512>>>(lng, lnb, pw, pb, cb, sb, memw, memb, semw, semb, t);      // 3 on t==0
    }

    k_prep_dec<<<dim3(Vv/32, D2/32), 256>>>(decW);
    k_dec<<<NPART, 256, SMEM_MMA>>>(decb, out);
    k_fin<<<1, 256>>>(out);
    (void)in_sizes; (void)n_in; (void)out_size;
}

// round 12
// speedup vs baseline: 1.1412x; 1.1412x over previous
#include <cuda_runtime.h>
#include <cuda_bf16.h>
#include <math.h>
#include <stdint.h>

#define Bv 128
#define Dv 512
#define D2 1024
#define Vv 32000
#define Av 64
#define MAXREC 12
#define KCAP 1664
#define SCALE 0.044194173824159216f
#define NPART (Vv/128)   // 250
#define NCLIN 3072

// k_par roles: mem first, palette second, MMA last (scheduling overlap)
#define B_PAL0 128
#define B_VQ0  384
#define B_CL0  634
#define NB_PAR 658

typedef __nv_bfloat16 bf16;

__device__ __align__(16) float g_gr[Bv*Dv], g_gi[Bv*Dv];
__device__ __align__(16) float g_qr[Bv*Dv], g_qi[Bv*Dv], g_kr[Bv*Dv], g_ki[Bv*Dv], g_vr[Bv*Dv], g_vi[Bv*Dv];
__device__ float g_ssalv[Bv], g_ssala[Bv];
__device__ __align__(16) float g_vresp[Bv*Dv], g_aresp[Bv*Dv];
__device__ __align__(16) float g_rec[Bv*Dv];
__device__ __align__(16) float g_K[KCAP*Dv], g_Vm[KCAP*Dv];
__device__ float g_kn[KCAP];
__device__ float g_grn[Bv];
__device__ float g_cn[Vv];
__device__ float g_pmin[NPART*Bv];
__device__ int   g_pidx[NPART*Bv];
__device__ float g_vqrows[MAXREC*Bv];

__device__ __align__(16) bf16 g_zh[Bv*D2], g_zl[Bv*D2];
__device__ __align__(16) bf16 g_wh[NCLIN*D2], g_wl[NCLIN*D2];
__device__ __align__(16) bf16 g_cbh[(size_t)Vv*D2], g_cbl[(size_t)Vv*D2];
__device__ __align__(16) bf16 g_dTh[(size_t)Vv*D2], g_dTl[(size_t)Vv*D2];

template<int NT>
__device__ __forceinline__ float blockSum(float v, float* sh) {
    int tid = threadIdx.x;
    #pragma unroll
    for (int o = 16; o > 0; o >>= 1) v += __shfl_down_sync(0xffffffffu, v, o);
    if ((tid & 31) == 0) sh[tid >> 5] = v;
    __syncthreads();
    float r = (tid < (NT/32)) ? sh[tid] : 0.f;
    if (tid < 32) {
        #pragma unroll
        for (int o = 16; o > 0; o >>= 1) r += __shfl_down_sync(0xffffffffu, r, o);
        if (tid == 0) sh[0] = r;
    }
    __syncthreads();
    float out = sh[0];
    __syncthreads();
    return out;
}

template<int NT>
__device__ __forceinline__ float blockMax(float v, float* sh) {
    int tid = threadIdx.x;
    #pragma unroll
    for (int o = 16; o > 0; o >>= 1) v = fmaxf(v, __shfl_down_sync(0xffffffffu, v, o));
    if ((tid & 31) == 0) sh[tid >> 5] = v;
    __syncthreads();
    float r = (tid < (NT/32)) ? sh[tid] : -3.0e38f;
    if (tid < 32) {
        #pragma unroll
        for (int o = 16; o > 0; o >>= 1) r = fmaxf(r, __shfl_down_sync(0xffffffffu, r, o));
        if (tid == 0) sh[0] = r;
    }
    __syncthreads();
    float out = sh[0];
    __syncthreads();
    return out;
}

__device__ __forceinline__ void splitStore(float v, bf16* ph, bf16* pl) {
    bf16 h = __float2bfloat16(v);
    *ph = h;
    *pl = __float2bfloat16(v - __bfloat162float(h));
}

// ===== merged prep: codebook split+norms / dec transpose+split / state+mem+W init =====
// blocks [0, 32000): cb rows; [32000, 64000): dec 32x32 tiles; [64000, 64256): init; [64256, 65792): W
__global__ void k_prep(const float* cb, const float* W,
                       const int* x, const float* embW, const float* mk, const float* mv,
                       const float* Wqr, const float* Wqi, const float* Wkr,
                       const float* Wki, const float* Wvr, const float* Wvi) {
    __shared__ float sh[8];
    __shared__ float tile[32][33];
    int bid = blockIdx.x, tid = threadIdx.x;
    if (bid < Vv) {
        int j = bid;
        const float* c = cb + (size_t)j * D2;
        float s = 0.f;
        for (int k = tid; k < D2; k += 256) {
            float v = c[k];
            s += v*v;
            splitStore(v, &g_cbh[(size_t)j*D2+k], &g_cbl[(size_t)j*D2+k]);
        }
        float tot = blockSum<256>(s, sh);
        if (tid == 0) g_cn[j] = tot;
    } else if (bid < 2*Vv) {
        int idx = bid - Vv;
        int n0 = (idx % 1000) * 32, k0 = (idx / 1000) * 32;
        int tx = tid & 31, ty = tid >> 5;
        for (int r = ty; r < 32; r += 8)
            tile[r][tx] = W[(size_t)(k0+r)*Vv + n0 + tx];
        __syncthreads();
        for (int r = ty; r < 32; r += 8) {
            float v = tile[tx][r];
            size_t o = (size_t)(n0+r)*D2 + k0 + tx;
            splitStore(v, &g_dTh[o], &g_dTl[o]);
        }
    } else if (bid < 2*Vv + Bv) {
        int i = bid - 2*Vv;
        const float* e = embW + (size_t)x[i] * D2;
        float sq = 0.f;
        for (int d = tid; d < Dv; d += 256) {
            float r = e[d], im = e[Dv+d];
            g_gr[i*Dv+d] = r; g_gi[i*Dv+d] = im;
            splitStore(r,  &g_zh[i*D2+d],    &g_zl[i*D2+d]);
            splitStore(im, &g_zh[i*D2+Dv+d], &g_zl[i*D2+Dv+d]);
            sq += r*r;
        }
        float tot = blockSum<256>(sq, sh);
        if (tid == 0) g_grn[i] = 1.f / fmaxf(sqrtf(tot), 1e-12f);
    } else if (bid < 2*Vv + 2*Bv) {
        int i = bid - 2*Vv - Bv;
        float s = 0.f;
        for (int d = tid; d < Dv; d += 256) {
            float k = mk[i*Dv+d];
            g_K[(1536+i)*Dv+d] = k;
            g_Vm[(1536+i)*Dv+d] = mv[i*Dv+d];
            s += k*k;
        }
        float tot = blockSum<256>(s, sh);
        if (tid == 0) g_kn[1536+i] = 1.f / fmaxf(sqrtf(tot), 1e-12f);
    } else {
        int n = (bid - 2*Vv - 2*Bv) * 2 + (tid >> 7);
        int tl = tid & 127;
        int grp = n >> 9, c = n & 511;
        const float *s1, *s2; float sg2;
        switch (grp) {
            case 0: s1=Wqr; s2=Wqi; sg2=-1.f; break;
            case 1: s1=Wqi; s2=Wqr; sg2= 1.f; break;
            case 2: s1=Wkr; s2=Wki; sg2=-1.f; break;
            case 3: s1=Wki; s2=Wkr; sg2= 1.f; break;
            case 4: s1=Wvr; s2=Wvi; sg2=-1.f; break;
            default:s1=Wvi; s2=Wvr; sg2= 1.f; break;
        }
        for (int k = tl; k < Dv; k += 128) {
            float v1 = s1[c*Dv + k];
            float v2 = sg2 * s2[c*Dv + k];
            splitStore(v1, &g_wh[n*D2+k],    &g_wl[n*D2+k]);
            splitStore(v2, &g_wh[n*D2+Dv+k], &g_wl[n*D2+Dv+k]);
        }
    }
}
#define NB_PREP (2*Vv + 2*Bv + NCLIN/2)

#define MMA16816(c, a, b) \
    asm volatile("mma.sync.aligned.m16n8k16.row.col.f32.bf16.bf16.f32 " \
        "{%0,%1,%2,%3},{%4,%5,%6,%7},{%8,%9},{%0,%1,%2,%3};" \
        : "+f"(c[0]), "+f"(c[1]), "+f"(c[2]), "+f"(c[3]) \
        : "r"(a[0]), "r"(a[1]), "r"(a[2]), "r"(a[3]), "r"(b[0]), "r"(b[1]))

#define LDSM4(d0, d1, d2, d3, addr) \
    asm volatile("ldmatrix.sync.aligned.m8n8.x4.shared.b16 {%0,%1,%2,%3}, [%4];" \
        : "=r"(d0), "=r"(d1), "=r"(d2), "=r"(d3) : "r"(addr))

#define CPA16(dst, src) \
    asm volatile("cp.async.cg.shared.global [%0], [%1], 16;" :: "r"(dst), "l"(src))

__device__ __forceinline__ void updMin(float v, int ix, float& bv, int& bi) {
    if (v < bv || (v == bv && ix < bi)) { bv = v; bi = ix; }
}

#define TP 40
#define SARR (128*TP*2)
#define SSTG (4*SARR)
#define SMEM_MMA (2*SSTG)

template<bool VQMODE>
__device__ __forceinline__ void mma_tile(char* dsm, int n0,
                                         const bf16* __restrict__ Bhp,
                                         const bf16* __restrict__ Blp, int pbid) {
    const uint32_t sb = (uint32_t)__cvta_generic_to_shared(dsm);
    const int tid = threadIdx.x;
    const int wid = tid >> 5, lane = tid & 31;
    const int wm = wid >> 2, wn = wid & 3;
    const int g = lane >> 2, tig = lane & 3;
    const int tg = lane >> 3, tr = lane & 7;
    const int a_row = ((tg & 1) << 3) + tr;
    const int a_col = (tg >> 1) << 3;
    const int b_row = ((tg >> 1) << 3) + tr;
    const int b_col = (tg & 1) << 3;

    float acc[4][4][4];
    #pragma unroll
    for (int a = 0; a < 4; a++)
        #pragma unroll
        for (int b = 0; b < 4; b++)
            #pragma unroll
            for (int c = 0; c < 4; c++) acc[a][b][c] = 0.f;

    const int zr0 = tid >> 2,         zs0 = (tid & 3) * 8;
    const int zr1 = (tid + 256) >> 2, zs1 = ((tid + 256) & 3) * 8;

    auto loadStage = [&](int stg, int k0) {
        uint32_t s0 = sb + stg * SSTG;
        CPA16(s0 +            (zr0*TP + zs0)*2, &g_zh[(size_t)zr0*D2 + k0 + zs0]);
        CPA16(s0 +            (zr1*TP + zs1)*2, &g_zh[(size_t)zr1*D2 + k0 + zs1]);
        CPA16(s0 +   SARR +   (zr0*TP + zs0)*2, &g_zl[(size_t)zr0*D2 + k0 + zs0]);
        CPA16(s0 +   SARR +   (zr1*TP + zs1)*2, &g_zl[(size_t)zr1*D2 + k0 + zs1]);
        CPA16(s0 + 2*SARR +   (zr0*TP + zs0)*2, &Bhp[(size_t)(n0+zr0)*D2 + k0 + zs0]);
        CPA16(s0 + 2*SARR +   (zr1*TP + zs1)*2, &Bhp[(size_t)(n0+zr1)*D2 + k0 + zs1]);
        CPA16(s0 + 3*SARR +   (zr0*TP + zs0)*2, &Blp[(size_t)(n0+zr0)*D2 + k0 + zs0]);
        CPA16(s0 + 3*SARR +   (zr1*TP + zs1)*2, &Blp[(size_t)(n0+zr1)*D2 + k0 + zs1]);
        asm volatile("cp.async.commit_group;");
    };

    loadStage(0, 0);

    const int NKC = D2 / 32;
    for (int kc = 0; kc < NKC; kc++) {
        if (kc + 1 < NKC) {
            loadStage((kc + 1) & 1, (kc + 1) * 32);
            asm volatile("cp.async.wait_group 1;");
        } else {
            asm volatile("cp.async.wait_group 0;");
        }
        __syncthreads();

        const uint32_t s0 = sb + (kc & 1) * SSTG;
        #pragma unroll
        for (int sub = 0; sub < 2; sub++) {
            const int kb = sub * 16;
            uint32_t af[4][4], bh2[4][2], bl2[4][2];
            #pragma unroll
            for (int fm = 0; fm < 4; fm++) {
                uint32_t addr = s0 + ((wm*64 + fm*16 + a_row)*TP + kb + a_col)*2;
                LDSM4(af[fm][0], af[fm][1], af[fm][2], af[fm][3], addr);
            }
            #pragma unroll
            for (int p = 0; p < 2; p++) {
                uint32_t addr = s0 + 2*SARR + ((wn*32 + p*16 + b_row)*TP + kb + b_col)*2;
                LDSM4(bh2[2*p][0], bh2[2*p][1], bh2[2*p+1][0], bh2[2*p+1][1], addr);
            }
            #pragma unroll
            for (int fm = 0; fm < 4; fm++)
                #pragma unroll
                for (int fn = 0; fn < 4; fn++) MMA16816(acc[fm][fn], af[fm], bh2[fn]);
            #pragma unroll
            for (int p = 0; p < 2; p++) {
                uint32_t addr = s0 + 3*SARR + ((wn*32 + p*16 + b_row)*TP + kb + b_col)*2;
                LDSM4(bl2[2*p][0], bl2[2*p][1], bl2[2*p+1][0], bl2[2*p+1][1], addr);
            }
            #pragma unroll
            for (int fm = 0; fm < 4; fm++)
                #pragma unroll
                for (int fn = 0; fn < 4; fn++) MMA16816(acc[fm][fn], af[fm], bl2[fn]);
            #pragma unroll
            for (int fm = 0; fm < 4; fm++) {
                uint32_t addr = s0 + SARR + ((wm*64 + fm*16 + a_row)*TP + kb + a_col)*2;
                LDSM4(af[fm][0], af[fm][1], af[fm][2], af[fm][3], addr);
            }
            #pragma unroll
            for (int fm = 0; fm < 4; fm++)
                #pragma unroll
                for (int fn = 0; fn < 4; fn++) MMA16816(acc[fm][fn], af[fm], bh2[fn]);
        }
        __syncthreads();
    }

    if (!VQMODE) {
        float* outs[6] = {g_qr, g_qi, g_kr, g_ki, g_vr, g_vi};
        #pragma unroll
        for (int fm = 0; fm < 4; fm++) {
            int r = wm*64 + fm*16 + g;
            #pragma unroll
            for (int fn = 0; fn < 4; fn++) {
                int gcol = n0 + wn*32 + fn*8 + tig*2;
                float* dst = outs[gcol >> 9];
                int c = gcol & 511;
                *(float2*)&dst[r*Dv + c]     = make_float2(acc[fm][fn][0], acc[fm][fn][1]);
                *(float2*)&dst[(r+8)*Dv + c] = make_float2(acc[fm][fn][2], acc[fm][fn][3]);
            }
        }
    } else {
        float* minv = (float*)dsm;
        int*   mini = (int*)(dsm + 128*4*sizeof(float));
        #pragma unroll
        for (int fm = 0; fm < 4; fm++) {
            int r0 = wm*64 + fm*16 + g;
            float bv0 = 3.0e38f, bv1 = 3.0e38f;
            int bi0 = 0x7fffffff, bi1 = 0x7fffffff;
            #pragma unroll
            for (int fn = 0; fn < 4; fn++) {
                int gcol = n0 + wn*32 + fn*8 + tig*2;
                float cn0 = g_cn[gcol], cn1 = g_cn[gcol+1];
                updMin(cn0 - 2.f*acc[fm][fn][0], gcol,   bv0, bi0);
                updMin(cn1 - 2.f*acc[fm][fn][1], gcol+1, bv0, bi0);
                updMin(cn0 - 2.f*acc[fm][fn][2], gcol,   bv1, bi1);
                updMin(cn1 - 2.f*acc[fm][fn][3], gcol+1, bv1, bi1);
            }
            #pragma unroll
            for (int o = 1; o <= 2; o <<= 1) {
                float ov = __shfl_xor_sync(0xffffffffu, bv0, o);
                int   oi = __shfl_xor_sync(0xffffffffu, bi0, o);
                updMin(ov, oi, bv0, bi0);
                ov = __shfl_xor_sync(0xffffffffu, bv1, o);
                oi = __shfl_xor_sync(0xffffffffu, bi1, o);
                updMin(ov, oi, bv1, bi1);
            }
            if (tig == 0) {
                minv[r0*4 + wn] = bv0; mini[r0*4 + wn] = bi0;
                minv[(r0+8)*4 + wn] = bv1; mini[(r0+8)*4 + wn] = bi1;
            }
        }
        __syncthreads();
        if (tid < 128) {
            float bv = 3.0e38f; int bi = 0x7fffffff;
            #pragma unroll
            for (int w = 0; w < 4; w++) updMin(minv[tid*4+w], mini[tid*4+w], bv, bi);
            g_pmin[pbid*Bv + tid] = bv;
            g_pidx[pbid*Bv + tid] = bi;
        }
    }
}

// ===== fused parallel kernel: mem + palette first (overlap), then VQ + clin MMA =====
__global__ __launch_bounds__(256, 2) void k_par(int off, int M,
                                                const float* __restrict__ vis,
                                                const float* __restrict__ aud,
                                                const float* __restrict__ sw) {
    extern __shared__ __align__(16) char dsm[];
    int bid = blockIdx.x, tid = threadIdx.x;

    if (bid < B_PAL0) {
        // ---- memory attention + fused push ----
        float* mg  = (float*)dsm;
        float* mlg = mg + 512;
        float* msh = mlg + 1536;
        int i = bid;
        for (int k = tid; k < Dv; k += 256) mg[k] = g_gr[i*Dv+k];
        __syncthreads();
        float rni = g_grn[i];
        float lmax = -3.0e38f;
        for (int m = tid; m < M; m += 256) {
            const float* kp = &g_K[(size_t)(off+m)*Dv];
            float s0 = 0.f, s1 = 0.f, s2 = 0.f, s3 = 0.f;
            for (int k = 0; k < Dv; k += 16) {
                float4 a = *(const float4*)&kp[k];
                float4 b = *(const float4*)&kp[k+4];
                float4 c = *(const float4*)&kp[k+8];
                float4 d = *(const float4*)&kp[k+12];
                s0 += mg[k]*a.x + mg[k+1]*a.y + mg[k+2]*a.z + mg[k+3]*a.w;
                s1 += mg[k+4]*b.x + mg[k+5]*b.y + mg[k+6]*b.z + mg[k+7]*b.w;
                s2 += mg[k+8]*c.x + mg[k+9]*c.y + mg[k+10]*c.z + mg[k+11]*c.w;
                s3 += mg[k+12]*d.x + mg[k+13]*d.y + mg[k+14]*d.z + mg[k+15]*d.w;
            }
            float l = 5.f * ((s0+s1)+(s2+s3)) * rni * g_kn[off+m];
            mlg[m] = l;
            lmax = fmaxf(lmax, l);
        }
        float mx = blockMax<256>(lmax, msh);
        float lsum = 0.f;
        for (int m = tid; m < M; m += 256) { float e = expf(mlg[m]-mx); mlg[m] = e; lsum += e; }
        float sum = blockSum<256>(lsum, msh);
        float inv = 1.f / sum;
        float a00 = 0.f, a01 = 0.f, a10 = 0.f, a11 = 0.f;
        int m = 0;
        for (; m + 1 < M; m += 2) {
            float w0 = mlg[m], w1 = mlg[m+1];
            const float* vp0 = &g_Vm[(size_t)(off+m)*Dv];
            const float* vp1 = vp0 + Dv;
            a00 += w0 * vp0[tid]; a01 += w0 * vp0[tid+256];
            a10 += w1 * vp1[tid]; a11 += w1 * vp1[tid+256];
        }
        if (m < M) {
            float w0 = mlg[m];
            const float* vp0 = &g_Vm[(size_t)(off+m)*Dv];
            a00 += w0 * vp0[tid]; a01 += w0 * vp0[tid+256];
        }
        g_rec[i*Dv + tid]       = (a00 + a10) * inv;
        g_rec[i*Dv + tid + 256] = (a01 + a11) * inv;
        {
            int noff = off - 128;
            float v0 = mg[tid], v1 = mg[tid + 256];
            g_K [(size_t)(noff+i)*Dv + tid]       = v0;
            g_K [(size_t)(noff+i)*Dv + tid + 256] = v1;
            g_Vm[(size_t)(noff+i)*Dv + tid]       = v0;
            g_Vm[(size_t)(noff+i)*Dv + tid + 256] = v1;
            if (tid == 0) g_kn[noff+i] = rni;
        }
    } else if (bid < B_VQ0) {
        // ---- palette ----
        float* pg  = (float*)dsm;
        float* plg = pg + 512;
        float* psh = plg + 64;
        int r = bid - B_PAL0;
        int i = r >> 1, z = r & 1;
        const float* src = z ? g_gi : g_gr;
        const float* P   = z ? aud : vis;
        float* resp      = z ? g_aresp : g_vresp;
        const float* swp = sw + z*Dv;
        for (int k = tid; k < Dv; k += 256) pg[k] = src[i*Dv+k];
        __syncthreads();
        {
            int a = tid >> 2, part = tid & 3;
            float s = 0.f;
            const float* pr = &P[a*Dv + part*128];
            const float* gq = &pg[part*128];
            for (int k = 0; k < 128; k += 4) {
                float4 p4 = *(const float4*)&pr[k];
                s += gq[k]*p4.x + gq[k+1]*p4.y + gq[k+2]*p4.z + gq[k+3]*p4.w;
            }
            s += __shfl_xor_sync(0xffffffffu, s, 1);
            s += __shfl_xor_sync(0xffffffffu, s, 2);
            if (part == 0) plg[a] = s;
        }
        __syncthreads();
        if (tid == 0) {
            float mx = -3.0e38f;
            for (int a = 0; a < Av; a++) mx = fmaxf(mx, plg[a]);
            float su = 0.f;
            for (int a = 0; a < Av; a++) { float e = expf(plg[a]-mx); plg[a] = e; su += e; }
            float inv = 1.f/su;
            for (int a = 0; a < Av; a++) plg[a] *= inv;
        }
        __syncthreads();
        float sal = 0.f;
        for (int d = tid; d < Dv; d += 256) {
            float acc = 0.f;
            for (int a = 0; a < Av; a++) acc += plg[a] * P[a*Dv + d];
            resp[i*Dv + d] = acc;
            sal += acc * swp[d];
        }
        float st = blockSum<256>(sal, psh);
        if (tid == 0) { if (z) g_ssala[i] = st; else g_ssalv[i] = st; }
    } else if (bid < B_CL0) {
        mma_tile<true>(dsm, (bid - B_VQ0) * 128, g_cbh, g_cbl, bid - B_VQ0);
    } else {
        mma_tile<false>(dsm, (bid - B_CL0) * 128, g_wh, g_wl, 0);
    }
}

__global__ __launch_bounds__(256, 2) void k_dec(const float* __restrict__ bias,
                                                float* __restrict__ out) {
    extern __shared__ __align__(16) char dsm[];
    const uint32_t sb = (uint32_t)__cvta_generic_to_shared(dsm);
    const int tid = threadIdx.x;
    const int wid = tid >> 5, lane = tid & 31;
    const int wm = wid >> 2, wn = wid & 3;
    const int g = lane >> 2, tig = lane & 3;
    const int n0 = blockIdx.x * 128;
    const int tg = lane >> 3, tr = lane & 7;
    const int a_row = ((tg & 1) << 3) + tr;
    const int a_col = (tg >> 1) << 3;
    const int b_row = ((tg >> 1) << 3) + tr;
    const int b_col = (tg & 1) << 3;

    float acc[4][4][4];
    #pragma unroll
    for (int a = 0; a < 4; a++)
        #pragma unroll
        for (int b = 0; b < 4; b++)
            #pragma unroll
            for (int c = 0; c < 4; c++) acc[a][b][c] = 0.f;

    const int zr0 = tid >> 2,         zs0 = (tid & 3) * 8;
    const int zr1 = (tid + 256) >> 2, zs1 = ((tid + 256) & 3) * 8;

    auto loadStage = [&](int stg, int k0) {
        uint32_t s0 = sb + stg * SSTG;
        CPA16(s0 +            (zr0*TP + zs0)*2, &g_zh[(size_t)zr0*D2 + k0 + zs0]);
        CPA16(s0 +            (zr1*TP + zs1)*2, &g_zh[(size_t)zr1*D2 + k0 + zs1]);
        CPA16(s0 +   SARR +   (zr0*TP + zs0)*2, &g_zl[(size_t)zr0*D2 + k0 + zs0]);
        CPA16(s0 +   SARR +   (zr1*TP + zs1)*2, &g_zl[(size_t)zr1*D2 + k0 + zs1]);
        CPA16(s0 + 2*SARR +   (zr0*TP + zs0)*2, &g_dTh[(size_t)(n0+zr0)*D2 + k0 + zs0]);
        CPA16(s0 + 2*SARR +   (zr1*TP + zs1)*2, &g_dTh[(size_t)(n0+zr1)*D2 + k0 + zs1]);
        CPA16(s0 + 3*SARR +   (zr0*TP + zs0)*2, &g_dTl[(size_t)(n0+zr0)*D2 + k0 + zs0]);
        CPA16(s0 + 3*SARR +   (zr1*TP + zs1)*2, &g_dTl[(size_t)(n0+zr1)*D2 + k0 + zs1]);
        asm volatile("cp.async.commit_group;");
    };

    loadStage(0, 0);
    const int NKC = D2 / 32;
    for (int kc = 0; kc < NKC; kc++) {
        if (kc + 1 < NKC) {
            loadStage((kc + 1) & 1, (kc + 1) * 32);
            asm volatile("cp.async.wait_group 1;");
        } else {
            asm volatile("cp.async.wait_group 0;");
        }
        __syncthreads();
        const uint32_t s0 = sb + (kc & 1) * SSTG;
        #pragma unroll
        for (int sub = 0; sub < 2; sub++) {
            const int kb = sub * 16;
            uint32_t af[4][4], bh2[4][2], bl2[4][2];
            #pragma unroll
            for (int fm = 0; fm < 4; fm++) {
                uint32_t addr = s0 + ((wm*64 + fm*16 + a_row)*TP + kb + a_col)*2;
                LDSM4(af[fm][0], af[fm][1], af[fm][2], af[fm][3], addr);
            }
            #pragma unroll
            for (int p = 0; p < 2; p++) {
                uint32_t addr = s0 + 2*SARR + ((wn*32 + p*16 + b_row)*TP + kb + b_col)*2;
                LDSM4(bh2[2*p][0], bh2[2*p][1], bh2[2*p+1][0], bh2[2*p+1][1], addr);
            }
            #pragma unroll
            for (int fm = 0; fm < 4; fm++)
                #pragma unroll
                for (int fn = 0; fn < 4; fn++) MMA16816(acc[fm][fn], af[fm], bh2[fn]);
            #pragma unroll
            for (int p = 0; p < 2; p++) {
                uint32_t addr = s0 + 3*SARR + ((wn*32 + p*16 + b_row)*TP + kb + b_col)*2;
                LDSM4(bl2[2*p][0], bl2[2*p][1], bl2[2*p+1][0], bl2[2*p+1][1], addr);
            }
            #pragma unroll
            for (int fm = 0; fm < 4; fm++)
                #pragma unroll
                for (int fn = 0; fn < 4; fn++) MMA16816(acc[fm][fn], af[fm], bl2[fn]);
            #pragma unroll
            for (int fm = 0; fm < 4; fm++) {
                uint32_t addr = s0 + SARR + ((wm*64 + fm*16 + a_row)*TP + kb + a_col)*2;
                LDSM4(af[fm][0], af[fm][1], af[fm][2], af[fm][3], addr);
            }
            #pragma unroll
            for (int fm = 0; fm < 4; fm++)
                #pragma unroll
                for (int fn = 0; fn < 4; fn++) MMA16816(acc[fm][fn], af[fm], bh2[fn]);
        }
        __syncthreads();
    }
    #pragma unroll
    for (int fm = 0; fm < 4; fm++) {
        int r = wm*64 + fm*16 + g;
        #pragma unroll
        for (int fn = 0; fn < 4; fn++) {
            int gcol = n0 + wn*32 + fn*8 + tig*2;
            float b0 = bias[gcol], b1 = bias[gcol+1];
            *(float2*)&out[(size_t)r*Vv + gcol] =
                make_float2(acc[fm][fn][0] + b0, acc[fm][fn][1] + b1);
            *(float2*)&out[(size_t)(r+8)*Vv + gcol] =
                make_float2(acc[fm][fn][2] + b0, acc[fm][fn][3] + b1);
        }
    }
}

// ===== fused per-row kernel, 512 threads =====
__global__ __launch_bounds__(512) void k_row(const float* lng, const float* lnb,
        const float* pw, const float* pb, const float* cb, const float* sensb,
        const float* memw, const float* memb, const float* semw, const float* semb, int t) {
    __shared__ float q[D2];
    __shared__ float part[4][Bv];
    __shared__ float att[Bv];
    __shared__ float sh[16];
    __shared__ float w[4];
    __shared__ float sv[512]; __shared__ int si[512];
    int i = blockIdx.x, tid = threadIdx.x;

    {
        float bv = 3.0e38f; int bi = 0x7fffffff;
        if (tid < NPART) { bv = g_pmin[tid*Bv + i]; bi = g_pidx[tid*Bv + i]; }
        sv[tid] = bv; si[tid] = bi;
    }
    q[tid]      = g_qr[i*Dv + tid];
    q[Dv + tid] = g_qi[i*Dv + tid];
    __syncthreads();
    for (int s = 256; s > 0; s >>= 1) {
        if (tid < s) {
            float v = sv[tid+s]; int ix = si[tid+s];
            if (v < sv[tid] || (v == sv[tid] && ix < si[tid])) { sv[tid] = v; si[tid] = ix; }
        }
        __syncthreads();
    }
    int idx = si[0];
    const float* c = &cb[(size_t)idx*D2];

    {
        int j = tid & 127, seg = tid >> 7;
        const float* kv = (seg < 2) ? &g_kr[j*Dv + (seg & 1)*256]
                                    : &g_ki[j*Dv + (seg & 1)*256];
        const float* qv = &q[seg*256];
        float s0 = 0.f, s1 = 0.f;
        for (int k = 0; k < 256; k += 8) {
            float4 a = *(const float4*)&kv[k];
            float4 a2 = *(const float4*)&kv[k+4];
            s0 += qv[k]*a.x + qv[k+1]*a.y + qv[k+2]*a.z + qv[k+3]*a.w;
            s1 += qv[k+4]*a2.x + qv[k+5]*a2.y + qv[k+6]*a2.z + qv[k+7]*a2.w;
        }
        part[seg][j] = s0 + s1;
    }
    __syncthreads();
    float logit = (tid < 128)
        ? (part[0][tid] + part[1][tid] + part[2][tid] + part[3][tid]) * SCALE
        : -3.0e38f;
    float mx = blockMax<512>(logit, sh);
    float e = (tid < 128) ? expf(logit - mx) : 0.f;
    float es = blockSum<512>(e, sh);
    if (tid < 128) att[tid] = e / es;
    __syncthreads();

    float fr = 0.f, fi = 0.f;
    {
        const float* vr = &g_vr[tid];
        const float* vi = &g_vi[tid];
        for (int j = 0; j + 4 <= Bv; j += 4) {
            float w0 = att[j], w1 = att[j+1], w2 = att[j+2], w3 = att[j+3];
            fr += w0*vr[(j)*Dv] + w1*vr[(j+1)*Dv] + w2*vr[(j+2)*Dv] + w3*vr[(j+3)*Dv];
            fi += w0*vi[(j)*Dv] + w1*vi[(j+1)*Dv] + w2*vi[(j+2)*Dv] + w3*vi[(j+3)*Dv];
        }
    }
    float m = blockSum<512>(fr + fi, sh) * (1.f/1024.f);
    float d0 = fr - m, d1 = fi - m;
    float var = blockSum<512>(d0*d0 + d1*d1, sh) * (1.f/1024.f);
    float rstd = rsqrtf(var + 1e-5f);
    int c0 = tid, c2 = Dv + tid;
    float yr = d0*rstd*lng[c0] + lnb[c0];
    float yi = d1*rstd*lng[c2] + lnb[c2];
    float pacc = yr*pw[c0] + yi*pw[c2];
    float psal = blockSum<512>(pacc, sh);

    float recv = g_rec[i*Dv + tid];
    float md = recv * memw[tid];
    float mds = blockSum<512>(md, sh);
    float sd = c[c0]*semw[c0] + c[c2]*semw[c2];
    float sds = blockSum<512>(sd, sh);
    if (tid == 0) {
        float a0 = (psal + pb[0]) * 1.25f;
        float a1 = (g_ssalv[i] + g_ssala[i] + sensb[0]) * 1.25f;
        float a2 = (mds + memb[0]) * 1.25f;
        float a3 = (sds + semb[0]) * 1.25f;
        float mxx = fmaxf(fmaxf(a0,a1), fmaxf(a2,a3));
        float e0 = expf(a0-mxx), e1 = expf(a1-mxx), e2 = expf(a2-mxx), e3 = expf(a3-mxx);
        float inv = 1.f / (e0+e1+e2+e3);
        w[0]=e0*inv; w[1]=e1*inv; w[2]=e2*inv; w[3]=e3*inv;
    }
    __syncthreads();
    float w0 = w[0], w1 = w[1], w2 = w[2], w3 = w[3];
    int d = tid;
    float ogr = g_gr[i*Dv+d], ogi = g_gi[i*Dv+d];
    float cr = c[d], ci = c[Dv+d];
    float dr = cr-ogr, di = ci-ogi;
    float vql = dr*dr + di*di;
    float nr = w0*yr + w1*g_vresp[i*Dv+d] + w2*recv + w3*cr;
    float ni = w0*yi + w1*g_aresp[i*Dv+d]           + w3*ci;
    float ngr = 0.6f*ogr + 0.4f*nr, ngi = 0.6f*ogi + 0.4f*ni;
    g_gr[i*Dv+d] = ngr; g_gi[i*Dv+d] = ngi;
    float sq = ngr*ngr;
    splitStore(ngr, &g_zh[i*D2+d],    &g_zl[i*D2+d]);
    splitStore(ngi, &g_zh[i*D2+Dv+d], &g_zl[i*D2+Dv+d]);
    float sqt = blockSum<512>(sq, sh);
    float vqt = blockSum<512>(vql, sh);
    if (tid == 0) {
        g_grn[i] = 1.f / fmaxf(sqrtf(sqt), 1e-12f);
        g_vqrows[t*Bv + i] = vqt;
    }
}

__global__ void k_fin(float* out) {
    __shared__ float sh[8];
    int tid = threadIdx.x;
    float s = 0.f;
    for (int k = tid; k < MAXREC*Bv; k += 256) s += g_vqrows[k];
    float tot = blockSum<256>(s, sh);
    if (tid == 0) {
        out[(size_t)Bv*Vv]     = 1.25f * tot / 131072.f;
        out[(size_t)Bv*Vv + 1] = (float)MAXREC;
    }
}

extern "C" void kernel_launch(void* const* d_in, const int* in_sizes, int n_in,
                              void* d_out, int out_size) {
    const int*   x    = (const int*)d_in[0];
    const float* embW = (const float*)d_in[1];
    const float* Wqr  = (const float*)d_in[2];
    const float* Wqi  = (const float*)d_in[3];
    const float* Wkr  = (const float*)d_in[4];
    const float* Wki  = (const float*)d_in[5];
    const float* Wvr  = (const float*)d_in[6];
    const float* Wvi  = (const float*)d_in[7];
    const float* lng  = (const float*)d_in[8];
    const float* lnb  = (const float*)d_in[9];
    const float* pw   = (const float*)d_in[10];
    const float* pb   = (const float*)d_in[11];
    const float* vis  = (const float*)d_in[12];
    const float* aud  = (const float*)d_in[13];
    const float* sw   = (const float*)d_in[14];
    const float* sb   = (const float*)d_in[15];
    const float* mk   = (const float*)d_in[16];
    const float* mv   = (const float*)d_in[17];
    const float* memw = (const float*)d_in[18];
    const float* memb = (const float*)d_in[19];
    const float* cb   = (const float*)d_in[20];
    const float* semw = (const float*)d_in[21];
    const float* semb = (const float*)d_in[22];
    const float* decW = (const float*)d_in[23];
    const float* decb = (const float*)d_in[24];
    float* out = (float*)d_out;

    cudaFuncSetAttribute(k_par, cudaFuncAttributeMaxDynamicSharedMemorySize, SMEM_MMA);
    cudaFuncSetAttribute(k_dec, cudaFuncAttributeMaxDynamicSharedMemorySize, SMEM_MMA);

    k_prep<<<NB_PREP, 256>>>(cb, decW, x, embW, mk, mv,
                             Wqr, Wqi, Wkr, Wki, Wvr, Wvi);                     // 0

    for (int t = 0; t < MAXREC; t++) {
        int off = 1536 - 128*t;
        int M   = 128 + 127*t;
        k_par<<<NB_PAR, 256, SMEM_MMA>>>(off, M, vis, aud, sw);                 // 1, 3(t=1)...
        k_row<<<Bv, 512>>>(lng, lnb, pw, pb, cb, sb, memw, memb, semw, semb, t);
    }

    k_dec<<<NPART, 256, SMEM_MMA>>>(decb, out);
    k_fin<<<1, 256>>>(out);
    (void)in_sizes; (void)n_in; (void)out_size;
}

// round 13
// speedup vs baseline: 1.1427x; 1.0013x over previous
#include <cuda_runtime.h>
#include <cuda_bf16.h>
#include <math.h>
#include <stdint.h>

#define Bv 128
#define Dv 512
#define D2 1024
#define Vv 32000
#define Av 64
#define MAXREC 12
#define KCAP 1664
#define SCALE 0.044194173824159216f
#define NPART (Vv/128)   // 250
#define NCLIN 3072

// k_par roles: mem first, palette second, MMA last (scheduling overlap)
#define B_PAL0 128
#define B_VQ0  384
#define B_CL0  634
#define NB_PAR 658

typedef __nv_bfloat16 bf16;

__device__ __align__(16) float g_gr[Bv*Dv], g_gi[Bv*Dv];
__device__ __align__(16) float g_qr[Bv*Dv], g_qi[Bv*Dv], g_kr[Bv*Dv], g_ki[Bv*Dv], g_vr[Bv*Dv], g_vi[Bv*Dv];
__device__ float g_ssalv[Bv], g_ssala[Bv];
__device__ __align__(16) float g_vresp[Bv*Dv], g_aresp[Bv*Dv];
__device__ __align__(16) float g_rec[Bv*Dv];
__device__ __align__(16) float g_K[KCAP*Dv], g_Vm[KCAP*Dv];
__device__ float g_kn[KCAP];
__device__ float g_grn[Bv];
__device__ float g_cn[Vv];
__device__ float g_pmin[NPART*Bv];
__device__ int   g_pidx[NPART*Bv];
__device__ float g_vqrows[MAXREC*Bv];

__device__ __align__(16) bf16 g_zh[Bv*D2], g_zl[Bv*D2];
__device__ __align__(16) bf16 g_wh[NCLIN*D2], g_wl[NCLIN*D2];
__device__ __align__(16) bf16 g_cbh[(size_t)Vv*D2], g_cbl[(size_t)Vv*D2];
__device__ __align__(16) bf16 g_dTh[(size_t)Vv*D2], g_dTl[(size_t)Vv*D2];

template<int NT>
__device__ __forceinline__ float blockSum(float v, float* sh) {
    int tid = threadIdx.x;
    #pragma unroll
    for (int o = 16; o > 0; o >>= 1) v += __shfl_down_sync(0xffffffffu, v, o);
    if ((tid & 31) == 0) sh[tid >> 5] = v;
    __syncthreads();
    float r = (tid < (NT/32)) ? sh[tid] : 0.f;
    if (tid < 32) {
        #pragma unroll
        for (int o = 16; o > 0; o >>= 1) r += __shfl_down_sync(0xffffffffu, r, o);
        if (tid == 0) sh[0] = r;
    }
    __syncthreads();
    float out = sh[0];
    __syncthreads();
    return out;
}

template<int NT>
__device__ __forceinline__ float blockMax(float v, float* sh) {
    int tid = threadIdx.x;
    #pragma unroll
    for (int o = 16; o > 0; o >>= 1) v = fmaxf(v, __shfl_down_sync(0xffffffffu, v, o));
    if ((tid & 31) == 0) sh[tid >> 5] = v;
    __syncthreads();
    float r = (tid < (NT/32)) ? sh[tid] : -3.0e38f;
    if (tid < 32) {
        #pragma unroll
        for (int o = 16; o > 0; o >>= 1) r = fmaxf(r, __shfl_down_sync(0xffffffffu, r, o));
        if (tid == 0) sh[0] = r;
    }
    __syncthreads();
    float out = sh[0];
    __syncthreads();
    return out;
}

__device__ __forceinline__ void splitStore(float v, bf16* ph, bf16* pl) {
    bf16 h = __float2bfloat16(v);
    *ph = h;
    *pl = __float2bfloat16(v - __bfloat162float(h));
}

// ===== merged prep: codebook split+norms / dec transpose+split / state+mem+W init =====
// blocks [0, 32000): cb rows; [32000, 64000): dec 32x32 tiles; [64000, 64256): init; [64256, 65792): W
__global__ void k_prep(const float* cb, const float* W,
                       const int* x, const float* embW, const float* mk, const float* mv,
                       const float* Wqr, const float* Wqi, const float* Wkr,
                       const float* Wki, const float* Wvr, const float* Wvi) {
    __shared__ float sh[8];
    __shared__ float tile[32][33];
    int bid = blockIdx.x, tid = threadIdx.x;
    if (bid < Vv) {
        int j = bid;
        const float* c = cb + (size_t)j * D2;
        float s = 0.f;
        for (int k = tid; k < D2; k += 256) {
            float v = c[k];
            s += v*v;
            splitStore(v, &g_cbh[(size_t)j*D2+k], &g_cbl[(size_t)j*D2+k]);
        }
        float tot = blockSum<256>(s, sh);
        if (tid == 0) g_cn[j] = tot;
    } else if (bid < 2*Vv) {
        int idx = bid - Vv;
        int n0 = (idx % 1000) * 32, k0 = (idx / 1000) * 32;
        int tx = tid & 31, ty = tid >> 5;
        for (int r = ty; r < 32; r += 8)
            tile[r][tx] = W[(size_t)(k0+r)*Vv + n0 + tx];
        __syncthreads();
        for (int r = ty; r < 32; r += 8) {
            float v = tile[tx][r];
            size_t o = (size_t)(n0+r)*D2 + k0 + tx;
            splitStore(v, &g_dTh[o], &g_dTl[o]);
        }
    } else if (bid < 2*Vv + Bv) {
        int i = bid - 2*Vv;
        const float* e = embW + (size_t)x[i] * D2;
        float sq = 0.f;
        for (int d = tid; d < Dv; d += 256) {
            float r = e[d], im = e[Dv+d];
            g_gr[i*Dv+d] = r; g_gi[i*Dv+d] = im;
            splitStore(r,  &g_zh[i*D2+d],    &g_zl[i*D2+d]);
            splitStore(im, &g_zh[i*D2+Dv+d], &g_zl[i*D2+Dv+d]);
            sq += r*r;
        }
        float tot = blockSum<256>(sq, sh);
        if (tid == 0) g_grn[i] = 1.f / fmaxf(sqrtf(tot), 1e-12f);
    } else if (bid < 2*Vv + 2*Bv) {
        int i = bid - 2*Vv - Bv;
        float s = 0.f;
        for (int d = tid; d < Dv; d += 256) {
            float k = mk[i*Dv+d];
            g_K[(1536+i)*Dv+d] = k;
            g_Vm[(1536+i)*Dv+d] = mv[i*Dv+d];
            s += k*k;
        }
        float tot = blockSum<256>(s, sh);
        if (tid == 0) g_kn[1536+i] = 1.f / fmaxf(sqrtf(tot), 1e-12f);
    } else {
        int n = (bid - 2*Vv - 2*Bv) * 2 + (tid >> 7);
        int tl = tid & 127;
        int grp = n >> 9, c = n & 511;
        const float *s1, *s2; float sg2;
        switch (grp) {
            case 0: s1=Wqr; s2=Wqi; sg2=-1.f; break;
            case 1: s1=Wqi; s2=Wqr; sg2= 1.f; break;
            case 2: s1=Wkr; s2=Wki; sg2=-1.f; break;
            case 3: s1=Wki; s2=Wkr; sg2= 1.f; break;
            case 4: s1=Wvr; s2=Wvi; sg2=-1.f; break;
            default:s1=Wvi; s2=Wvr; sg2= 1.f; break;
        }
        for (int k = tl; k < Dv; k += 128) {
            float v1 = s1[c*Dv + k];
            float v2 = sg2 * s2[c*Dv + k];
            splitStore(v1, &g_wh[n*D2+k],    &g_wl[n*D2+k]);
            splitStore(v2, &g_wh[n*D2+Dv+k], &g_wl[n*D2+Dv+k]);
        }
    }
}
#define NB_PREP (2*Vv + 2*Bv + NCLIN/2)

#define MMA16816(c, a, b) \
    asm volatile("mma.sync.aligned.m16n8k16.row.col.f32.bf16.bf16.f32 " \
        "{%0,%1,%2,%3},{%4,%5,%6,%7},{%8,%9},{%0,%1,%2,%3};" \
        : "+f"(c[0]), "+f"(c[1]), "+f"(c[2]), "+f"(c[3]) \
        : "r"(a[0]), "r"(a[1]), "r"(a[2]), "r"(a[3]), "r"(b[0]), "r"(b[1]))

#define LDSM4(d0, d1, d2, d3, addr) \
    asm volatile("ldmatrix.sync.aligned.m8n8.x4.shared.b16 {%0,%1,%2,%3}, [%4];" \
        : "=r"(d0), "=r"(d1), "=r"(d2), "=r"(d3) : "r"(addr))

#define CPA16(dst, src) \
    asm volatile("cp.async.cg.shared.global [%0], [%1], 16;" :: "r"(dst), "l"(src))

__device__ __forceinline__ void updMin(float v, int ix, float& bv, int& bi) {
    if (v < bv || (v == bv && ix < bi)) { bv = v; bi = ix; }
}

#define TP 40
#define SARR (128*TP*2)
#define SSTG (4*SARR)
#define SMEM_MMA (2*SSTG)

template<bool VQMODE>
__device__ __forceinline__ void mma_tile(char* dsm, int n0,
                                         const bf16* __restrict__ Bhp,
                                         const bf16* __restrict__ Blp, int pbid) {
    const uint32_t sb = (uint32_t)__cvta_generic_to_shared(dsm);
    const int tid = threadIdx.x;
    const int wid = tid >> 5, lane = tid & 31;
    const int wm = wid >> 2, wn = wid & 3;
    const int g = lane >> 2, tig = lane & 3;
    const int tg = lane >> 3, tr = lane & 7;
    const int a_row = ((tg & 1) << 3) + tr;
    const int a_col = (tg >> 1) << 3;
    const int b_row = ((tg >> 1) << 3) + tr;
    const int b_col = (tg & 1) << 3;

    float acc[4][4][4];
    #pragma unroll
    for (int a = 0; a < 4; a++)
        #pragma unroll
        for (int b = 0; b < 4; b++)
            #pragma unroll
            for (int c = 0; c < 4; c++) acc[a][b][c] = 0.f;

    const int zr0 = tid >> 2,         zs0 = (tid & 3) * 8;
    const int zr1 = (tid + 256) >> 2, zs1 = ((tid + 256) & 3) * 8;

    auto loadStage = [&](int stg, int k0) {
        uint32_t s0 = sb + stg * SSTG;
        CPA16(s0 +            (zr0*TP + zs0)*2, &g_zh[(size_t)zr0*D2 + k0 + zs0]);
        CPA16(s0 +            (zr1*TP + zs1)*2, &g_zh[(size_t)zr1*D2 + k0 + zs1]);
        CPA16(s0 +   SARR +   (zr0*TP + zs0)*2, &g_zl[(size_t)zr0*D2 + k0 + zs0]);
        CPA16(s0 +   SARR +   (zr1*TP + zs1)*2, &g_zl[(size_t)zr1*D2 + k0 + zs1]);
        CPA16(s0 + 2*SARR +   (zr0*TP + zs0)*2, &Bhp[(size_t)(n0+zr0)*D2 + k0 + zs0]);
        CPA16(s0 + 2*SARR +   (zr1*TP + zs1)*2, &Bhp[(size_t)(n0+zr1)*D2 + k0 + zs1]);
        CPA16(s0 + 3*SARR +   (zr0*TP + zs0)*2, &Blp[(size_t)(n0+zr0)*D2 + k0 + zs0]);
        CPA16(s0 + 3*SARR +   (zr1*TP + zs1)*2, &Blp[(size_t)(n0+zr1)*D2 + k0 + zs1]);
        asm volatile("cp.async.commit_group;");
    };

    loadStage(0, 0);

    const int NKC = D2 / 32;
    for (int kc = 0; kc < NKC; kc++) {
        if (kc + 1 < NKC) {
            loadStage((kc + 1) & 1, (kc + 1) * 32);
            asm volatile("cp.async.wait_group 1;");
        } else {
            asm volatile("cp.async.wait_group 0;");
        }
        __syncthreads();

        const uint32_t s0 = sb + (kc & 1) * SSTG;
        #pragma unroll
        for (int sub = 0; sub < 2; sub++) {
            const int kb = sub * 16;
            uint32_t af[4][4], bh2[4][2], bl2[4][2];
            #pragma unroll
            for (int fm = 0; fm < 4; fm++) {
                uint32_t addr = s0 + ((wm*64 + fm*16 + a_row)*TP + kb + a_col)*2;
                LDSM4(af[fm][0], af[fm][1], af[fm][2], af[fm][3], addr);
            }
            #pragma unroll
            for (int p = 0; p < 2; p++) {
                uint32_t addr = s0 + 2*SARR + ((wn*32 + p*16 + b_row)*TP + kb + b_col)*2;
                LDSM4(bh2[2*p][0], bh2[2*p][1], bh2[2*p+1][0], bh2[2*p+1][1], addr);
            }
            #pragma unroll
            for (int fm = 0; fm < 4; fm++)
                #pragma unroll
                for (int fn = 0; fn < 4; fn++) MMA16816(acc[fm][fn], af[fm], bh2[fn]);
            #pragma unroll
            for (int p = 0; p < 2; p++) {
                uint32_t addr = s0 + 3*SARR + ((wn*32 + p*16 + b_row)*TP + kb + b_col)*2;
                LDSM4(bl2[2*p][0], bl2[2*p][1], bl2[2*p+1][0], bl2[2*p+1][1], addr);
            }
            #pragma unroll
            for (int fm = 0; fm < 4; fm++)
                #pragma unroll
                for (int fn = 0; fn < 4; fn++) MMA16816(acc[fm][fn], af[fm], bl2[fn]);
            #pragma unroll
            for (int fm = 0; fm < 4; fm++) {
                uint32_t addr = s0 + SARR + ((wm*64 + fm*16 + a_row)*TP + kb + a_col)*2;
                LDSM4(af[fm][0], af[fm][1], af[fm][2], af[fm][3], addr);
            }
            #pragma unroll
            for (int fm = 0; fm < 4; fm++)
                #pragma unroll
                for (int fn = 0; fn < 4; fn++) MMA16816(acc[fm][fn], af[fm], bh2[fn]);
        }
        __syncthreads();
    }

    if (!VQMODE) {
        float* outs[6] = {g_qr, g_qi, g_kr, g_ki, g_vr, g_vi};
        #pragma unroll
        for (int fm = 0; fm < 4; fm++) {
            int r = wm*64 + fm*16 + g;
            #pragma unroll
            for (int fn = 0; fn < 4; fn++) {
                int gcol = n0 + wn*32 + fn*8 + tig*2;
                float* dst = outs[gcol >> 9];
                int c = gcol & 511;
                *(float2*)&dst[r*Dv + c]     = make_float2(acc[fm][fn][0], acc[fm][fn][1]);
                *(float2*)&dst[(r+8)*Dv + c] = make_float2(acc[fm][fn][2], acc[fm][fn][3]);
            }
        }
    } else {
        float* minv = (float*)dsm;
        int*   mini = (int*)(dsm + 128*4*sizeof(float));
        #pragma unroll
        for (int fm = 0; fm < 4; fm++) {
            int r0 = wm*64 + fm*16 + g;
            float bv0 = 3.0e38f, bv1 = 3.0e38f;
            int bi0 = 0x7fffffff, bi1 = 0x7fffffff;
            #pragma unroll
            for (int fn = 0; fn < 4; fn++) {
                int gcol = n0 + wn*32 + fn*8 + tig*2;
                float cn0 = g_cn[gcol], cn1 = g_cn[gcol+1];
                updMin(cn0 - 2.f*acc[fm][fn][0], gcol,   bv0, bi0);
                updMin(cn1 - 2.f*acc[fm][fn][1], gcol+1, bv0, bi0);
                updMin(cn0 - 2.f*acc[fm][fn][2], gcol,   bv1, bi1);
                updMin(cn1 - 2.f*acc[fm][fn][3], gcol+1, bv1, bi1);
            }
            #pragma unroll
            for (int o = 1; o <= 2; o <<= 1) {
                float ov = __shfl_xor_sync(0xffffffffu, bv0, o);
                int   oi = __shfl_xor_sync(0xffffffffu, bi0, o);
                updMin(ov, oi, bv0, bi0);
                ov = __shfl_xor_sync(0xffffffffu, bv1, o);
                oi = __shfl_xor_sync(0xffffffffu, bi1, o);
                updMin(ov, oi, bv1, bi1);
            }
            if (tig == 0) {
                minv[r0*4 + wn] = bv0; mini[r0*4 + wn] = bi0;
                minv[(r0+8)*4 + wn] = bv1; mini[(r0+8)*4 + wn] = bi1;
            }
        }
        __syncthreads();
        if (tid < 128) {
            float bv = 3.0e38f; int bi = 0x7fffffff;
            #pragma unroll
            for (int w = 0; w < 4; w++) updMin(minv[tid*4+w], mini[tid*4+w], bv, bi);
            g_pmin[pbid*Bv + tid] = bv;
            g_pidx[pbid*Bv + tid] = bi;
        }
    }
}

// ===== fused parallel kernel: mem + palette first (overlap), then VQ + clin MMA =====
__global__ __launch_bounds__(256, 2) void k_par(int off, int M,
                                                const float* __restrict__ vis,
                                                const float* __restrict__ aud,
                                                const float* __restrict__ sw) {
    extern __shared__ __align__(16) char dsm[];
    int bid = blockIdx.x, tid = threadIdx.x;

    if (bid < B_PAL0) {
        // ---- memory attention + fused push ----
        float* mg  = (float*)dsm;
        float* mlg = mg + 512;
        float* msh = mlg + 1536;
        int i = bid;
        for (int k = tid; k < Dv; k += 256) mg[k] = g_gr[i*Dv+k];
        __syncthreads();
        float rni = g_grn[i];
        float lmax = -3.0e38f;
        for (int m = tid; m < M; m += 256) {
            const float* kp = &g_K[(size_t)(off+m)*Dv];
            float s0 = 0.f, s1 = 0.f, s2 = 0.f, s3 = 0.f;
            for (int k = 0; k < Dv; k += 16) {
                float4 a = *(const float4*)&kp[k];
                float4 b = *(const float4*)&kp[k+4];
                float4 c = *(const float4*)&kp[k+8];
                float4 d = *(const float4*)&kp[k+12];
                s0 += mg[k]*a.x + mg[k+1]*a.y + mg[k+2]*a.z + mg[k+3]*a.w;
                s1 += mg[k+4]*b.x + mg[k+5]*b.y + mg[k+6]*b.z + mg[k+7]*b.w;
                s2 += mg[k+8]*c.x + mg[k+9]*c.y + mg[k+10]*c.z + mg[k+11]*c.w;
                s3 += mg[k+12]*d.x + mg[k+13]*d.y + mg[k+14]*d.z + mg[k+15]*d.w;
            }
            float l = 5.f * ((s0+s1)+(s2+s3)) * rni * g_kn[off+m];
            mlg[m] = l;
            lmax = fmaxf(lmax, l);
        }
        float mx = blockMax<256>(lmax, msh);
        float lsum = 0.f;
        for (int m = tid; m < M; m += 256) { float e = expf(mlg[m]-mx); mlg[m] = e; lsum += e; }
        float sum = blockSum<256>(lsum, msh);
        float inv = 1.f / sum;
        float a00 = 0.f, a01 = 0.f, a10 = 0.f, a11 = 0.f;
        int m = 0;
        for (; m + 1 < M; m += 2) {
            float w0 = mlg[m], w1 = mlg[m+1];
            const float* vp0 = &g_Vm[(size_t)(off+m)*Dv];
            const float* vp1 = vp0 + Dv;
            a00 += w0 * vp0[tid]; a01 += w0 * vp0[tid+256];
            a10 += w1 * vp1[tid]; a11 += w1 * vp1[tid+256];
        }
        if (m < M) {
            float w0 = mlg[m];
            const float* vp0 = &g_Vm[(size_t)(off+m)*Dv];
            a00 += w0 * vp0[tid]; a01 += w0 * vp0[tid+256];
        }
        g_rec[i*Dv + tid]       = (a00 + a10) * inv;
        g_rec[i*Dv + tid + 256] = (a01 + a11) * inv;
        {
            int noff = off - 128;
            float v0 = mg[tid], v1 = mg[tid + 256];
            g_K [(size_t)(noff+i)*Dv + tid]       = v0;
            g_K [(size_t)(noff+i)*Dv + tid + 256] = v1;
            g_Vm[(size_t)(noff+i)*Dv + tid]       = v0;
            g_Vm[(size_t)(noff+i)*Dv + tid + 256] = v1;
            if (tid == 0) g_kn[noff+i] = rni;
        }
    } else if (bid < B_VQ0) {
        // ---- palette ----
        float* pg  = (float*)dsm;
        float* plg = pg + 512;
        float* psh = plg + 64;
        int r = bid - B_PAL0;
        int i = r >> 1, z = r & 1;
        const float* src = z ? g_gi : g_gr;
        const float* P   = z ? aud : vis;
        float* resp      = z ? g_aresp : g_vresp;
        const float* swp = sw + z*Dv;
        for (int k = tid; k < Dv; k += 256) pg[k] = src[i*Dv+k];
        __syncthreads();
        {
            int a = tid >> 2, part = tid & 3;
            float s = 0.f;
            const float* pr = &P[a*Dv + part*128];
            const float* gq = &pg[part*128];
            for (int k = 0; k < 128; k += 4) {
                float4 p4 = *(const float4*)&pr[k];
                s += gq[k]*p4.x + gq[k+1]*p4.y + gq[k+2]*p4.z + gq[k+3]*p4.w;
            }
            s += __shfl_xor_sync(0xffffffffu, s, 1);
            s += __shfl_xor_sync(0xffffffffu, s, 2);
            if (part == 0) plg[a] = s;
        }
        __syncthreads();
        if (tid == 0) {
            float mx = -3.0e38f;
            for (int a = 0; a < Av; a++) mx = fmaxf(mx, plg[a]);
            float su = 0.f;
            for (int a = 0; a < Av; a++) { float e = expf(plg[a]-mx); plg[a] = e; su += e; }
            float inv = 1.f/su;
            for (int a = 0; a < Av; a++) plg[a] *= inv;
        }
        __syncthreads();
        float sal = 0.f;
        for (int d = tid; d < Dv; d += 256) {
            float acc = 0.f;
            for (int a = 0; a < Av; a++) acc += plg[a] * P[a*Dv + d];
            resp[i*Dv + d] = acc;
            sal += acc * swp[d];
        }
        float st = blockSum<256>(sal, psh);
        if (tid == 0) { if (z) g_ssala[i] = st; else g_ssalv[i] = st; }
    } else if (bid < B_CL0) {
        mma_tile<true>(dsm, (bid - B_VQ0) * 128, g_cbh, g_cbl, bid - B_VQ0);
    } else {
        mma_tile<false>(dsm, (bid - B_CL0) * 128, g_wh, g_wl, 0);
    }
}

__global__ __launch_bounds__(256, 2) void k_dec(const float* __restrict__ bias,
                                                float* __restrict__ out) {
    extern __shared__ __align__(16) char dsm[];
    const uint32_t sb = (uint32_t)__cvta_generic_to_shared(dsm);
    const int tid = threadIdx.x;
    const int wid = tid >> 5, lane = tid & 31;
    const int wm = wid >> 2, wn = wid & 3;
    const int g = lane >> 2, tig = lane & 3;
    const int n0 = blockIdx.x * 128;
    const int tg = lane >> 3, tr = lane & 7;
    const int a_row = ((tg & 1) << 3) + tr;
    const int a_col = (tg >> 1) << 3;
    const int b_row = ((tg >> 1) << 3) + tr;
    const int b_col = (tg & 1) << 3;

    float acc[4][4][4];
    #pragma unroll
    for (int a = 0; a < 4; a++)
        #pragma unroll
        for (int b = 0; b < 4; b++)
            #pragma unroll
            for (int c = 0; c < 4; c++) acc[a][b][c] = 0.f;

    const int zr0 = tid >> 2,         zs0 = (tid & 3) * 8;
    const int zr1 = (tid + 256) >> 2, zs1 = ((tid + 256) & 3) * 8;

    auto loadStage = [&](int stg, int k0) {
        uint32_t s0 = sb + stg * SSTG;
        CPA16(s0 +            (zr0*TP + zs0)*2, &g_zh[(size_t)zr0*D2 + k0 + zs0]);
        CPA16(s0 +            (zr1*TP + zs1)*2, &g_zh[(size_t)zr1*D2 + k0 + zs1]);
        CPA16(s0 +   SARR +   (zr0*TP + zs0)*2, &g_zl[(size_t)zr0*D2 + k0 + zs0]);
        CPA16(s0 +   SARR +   (zr1*TP + zs1)*2, &g_zl[(size_t)zr1*D2 + k0 + zs1]);
        CPA16(s0 + 2*SARR +   (zr0*TP + zs0)*2, &g_dTh[(size_t)(n0+zr0)*D2 + k0 + zs0]);
        CPA16(s0 + 2*SARR +   (zr1*TP + zs1)*2, &g_dTh[(size_t)(n0+zr1)*D2 + k0 + zs1]);
        CPA16(s0 + 3*SARR +   (zr0*TP + zs0)*2, &g_dTl[(size_t)(n0+zr0)*D2 + k0 + zs0]);
        CPA16(s0 + 3*SARR +   (zr1*TP + zs1)*2, &g_dTl[(size_t)(n0+zr1)*D2 + k0 + zs1]);
        asm volatile("cp.async.commit_group;");
    };

    loadStage(0, 0);
    const int NKC = D2 / 32;
    for (int kc = 0; kc < NKC; kc++) {
        if (kc + 1 < NKC) {
            loadStage((kc + 1) & 1, (kc + 1) * 32);
            asm volatile("cp.async.wait_group 1;");
        } else {
            asm volatile("cp.async.wait_group 0;");
        }
        __syncthreads();
        const uint32_t s0 = sb + (kc & 1) * SSTG;
        #pragma unroll
        for (int sub = 0; sub < 2; sub++) {
            const int kb = sub * 16;
            uint32_t af[4][4], bh2[4][2], bl2[4][2];
            #pragma unroll
            for (int fm = 0; fm < 4; fm++) {
                uint32_t addr = s0 + ((wm*64 + fm*16 + a_row)*TP + kb + a_col)*2;
                LDSM4(af[fm][0], af[fm][1], af[fm][2], af[fm][3], addr);
            }
            #pragma unroll
            for (int p = 0; p < 2; p++) {
                uint32_t addr = s0 + 2*SARR + ((wn*32 + p*16 + b_row)*TP + kb + b_col)*2;
                LDSM4(bh2[2*p][0], bh2[2*p][1], bh2[2*p+1][0], bh2[2*p+1][1], addr);
            }
            #pragma unroll
            for (int fm = 0; fm < 4; fm++)
                #pragma unroll
                for (int fn = 0; fn < 4; fn++) MMA16816(acc[fm][fn], af[fm], bh2[fn]);
            #pragma unroll
            for (int p = 0; p < 2; p++) {
                uint32_t addr = s0 + 3*SARR + ((wn*32 + p*16 + b_row)*TP + kb + b_col)*2;
                LDSM4(bl2[2*p][0], bl2[2*p][1], bl2[2*p+1][0], bl2[2*p+1][1], addr);
            }
            #pragma unroll
            for (int fm = 0; fm < 4; fm++)
                #pragma unroll
                for (int fn = 0; fn < 4; fn++) MMA16816(acc[fm][fn], af[fm], bl2[fn]);
            #pragma unroll
            for (int fm = 0; fm < 4; fm++) {
                uint32_t addr = s0 + SARR + ((wm*64 + fm*16 + a_row)*TP + kb + a_col)*2;
                LDSM4(af[fm][0], af[fm][1], af[fm][2], af[fm][3], addr);
            }
            #pragma unroll
            for (int fm = 0; fm < 4; fm++)
                #pragma unroll
                for (int fn = 0; fn < 4; fn++) MMA16816(acc[fm][fn], af[fm], bh2[fn]);
        }
        __syncthreads();
    }
    #pragma unroll
    for (int fm = 0; fm < 4; fm++) {
        int r = wm*64 + fm*16 + g;
        #pragma unroll
        for (int fn = 0; fn < 4; fn++) {
            int gcol = n0 + wn*32 + fn*8 + tig*2;
            float b0 = bias[gcol], b1 = bias[gcol+1];
            *(float2*)&out[(size_t)r*Vv + gcol] =
                make_float2(acc[fm][fn][0] + b0, acc[fm][fn][1] + b1);
            *(float2*)&out[(size_t)(r+8)*Vv + gcol] =
                make_float2(acc[fm][fn][2] + b0, acc[fm][fn][3] + b1);
        }
    }
}

// ===== fused per-row kernel, 512 threads =====
__global__ __launch_bounds__(512) void k_row(const float* lng, const float* lnb,
        const float* pw, const float* pb, const float* cb, const float* sensb,
        const float* memw, const float* memb, const float* semw, const float* semb, int t) {
    __shared__ float q[D2];
    __shared__ float part[4][Bv];
    __shared__ float att[Bv];
    __shared__ float sh[16];
    __shared__ float w[4];
    __shared__ float sv[512]; __shared__ int si[512];
    int i = blockIdx.x, tid = threadIdx.x;

    {
        float bv = 3.0e38f; int bi = 0x7fffffff;
        if (tid < NPART) { bv = g_pmin[tid*Bv + i]; bi = g_pidx[tid*Bv + i]; }
        sv[tid] = bv; si[tid] = bi;
    }
    q[tid]      = g_qr[i*Dv + tid];
    q[Dv + tid] = g_qi[i*Dv + tid];
    __syncthreads();
    for (int s = 256; s > 0; s >>= 1) {
        if (tid < s) {
            float v = sv[tid+s]; int ix = si[tid+s];
            if (v < sv[tid] || (v == sv[tid] && ix < si[tid])) { sv[tid] = v; si[tid] = ix; }
        }
        __syncthreads();
    }
    int idx = si[0];
    const float* c = &cb[(size_t)idx*D2];

    {
        int j = tid & 127, seg = tid >> 7;
        const float* kv = (seg < 2) ? &g_kr[j*Dv + (seg & 1)*256]
                                    : &g_ki[j*Dv + (seg & 1)*256];
        const float* qv = &q[seg*256];
        float s0 = 0.f, s1 = 0.f;
        for (int k = 0; k < 256; k += 8) {
            float4 a = *(const float4*)&kv[k];
            float4 a2 = *(const float4*)&kv[k+4];
            s0 += qv[k]*a.x + qv[k+1]*a.y + qv[k+2]*a.z + qv[k+3]*a.w;
            s1 += qv[k+4]*a2.x + qv[k+5]*a2.y + qv[k+6]*a2.z + qv[k+7]*a2.w;
        }
        part[seg][j] = s0 + s1;
    }
    __syncthreads();
    float logit = (tid < 128)
        ? (part[0][tid] + part[1][tid] + part[2][tid] + part[3][tid]) * SCALE
        : -3.0e38f;
    float mx = blockMax<512>(logit, sh);
    float e = (tid < 128) ? expf(logit - mx) : 0.f;
    float es = blockSum<512>(e, sh);
    if (tid < 128) att[tid] = e / es;
    __syncthreads();

    float fr = 0.f, fi = 0.f;
    {
        const float* vr = &g_vr[tid];
        const float* vi = &g_vi[tid];
        for (int j = 0; j + 4 <= Bv; j += 4) {
            float w0 = att[j], w1 = att[j+1], w2 = att[j+2], w3 = att[j+3];
            fr += w0*vr[(j)*Dv] + w1*vr[(j+1)*Dv] + w2*vr[(j+2)*Dv] + w3*vr[(j+3)*Dv];
            fi += w0*vi[(j)*Dv] + w1*vi[(j+1)*Dv] + w2*vi[(j+2)*Dv] + w3*vi[(j+3)*Dv];
        }
    }
    float m = blockSum<512>(fr + fi, sh) * (1.f/1024.f);
    float d0 = fr - m, d1 = fi - m;
    float var = blockSum<512>(d0*d0 + d1*d1, sh) * (1.f/1024.f);
    float rstd = rsqrtf(var + 1e-5f);
    int c0 = tid, c2 = Dv + tid;
    float yr = d0*rstd*lng[c0] + lnb[c0];
    float yi = d1*rstd*lng[c2] + lnb[c2];
    float pacc = yr*pw[c0] + yi*pw[c2];
    float psal = blockSum<512>(pacc, sh);

    float recv = g_rec[i*Dv + tid];
    float md = recv * memw[tid];
    float mds = blockSum<512>(md, sh);
    float sd = c[c0]*semw[c0] + c[c2]*semw[c2];
    float sds = blockSum<512>(sd, sh);
    if (tid == 0) {
        float a0 = (psal + pb[0]) * 1.25f;
        float a1 = (g_ssalv[i] + g_ssala[i] + sensb[0]) * 1.25f;
        float a2 = (mds + memb[0]) * 1.25f;
        float a3 = (sds + semb[0]) * 1.25f;
        float mxx = fmaxf(fmaxf(a0,a1), fmaxf(a2,a3));
        float e0 = expf(a0-mxx), e1 = expf(a1-mxx), e2 = expf(a2-mxx), e3 = expf(a3-mxx);
        float inv = 1.f / (e0+e1+e2+e3);
        w[0]=e0*inv; w[1]=e1*inv; w[2]=e2*inv; w[3]=e3*inv;
    }
    __syncthreads();
    float w0 = w[0], w1 = w[1], w2 = w[2], w3 = w[3];
    int d = tid;
    float ogr = g_gr[i*Dv+d], ogi = g_gi[i*Dv+d];
    float cr = c[d], ci = c[Dv+d];
    float dr = cr-ogr, di = ci-ogi;
    float vql = dr*dr + di*di;
    float nr = w0*yr + w1*g_vresp[i*Dv+d] + w2*recv + w3*cr;
    float ni = w0*yi + w1*g_aresp[i*Dv+d]           + w3*ci;
    float ngr = 0.6f*ogr + 0.4f*nr, ngi = 0.6f*ogi + 0.4f*ni;
    g_gr[i*Dv+d] = ngr; g_gi[i*Dv+d] = ngi;
    float sq = ngr*ngr;
    splitStore(ngr, &g_zh[i*D2+d],    &g_zl[i*D2+d]);
    splitStore(ngi, &g_zh[i*D2+Dv+d], &g_zl[i*D2+Dv+d]);
    float sqt = blockSum<512>(sq, sh);
    float vqt = blockSum<512>(vql, sh);
    if (tid == 0) {
        g_grn[i] = 1.f / fmaxf(sqrtf(sqt), 1e-12f);
        g_vqrows[t*Bv + i] = vqt;
    }
}

__global__ void k_fin(float* out) {
    __shared__ float sh[8];
    int tid = threadIdx.x;
    float s = 0.f;
    for (int k = tid; k < MAXREC*Bv; k += 256) s += g_vqrows[k];
    float tot = blockSum<256>(s, sh);
    if (tid == 0) {
        out[(size_t)Bv*Vv]     = 1.25f * tot / 131072.f;
        out[(size_t)Bv*Vv + 1] = (float)MAXREC;
    }
}

extern "C" void kernel_launch(void* const* d_in, const int* in_sizes, int n_in,
                              void* d_out, int out_size) {
    const int*   x    = (const int*)d_in[0];
    const float* embW = (const float*)d_in[1];
    const float* Wqr  = (const float*)d_in[2];
    const float* Wqi  = (const float*)d_in[3];
    const float* Wkr  = (const float*)d_in[4];
    const float* Wki  = (const float*)d_in[5];
    const float* Wvr  = (const float*)d_in[6];
    const float* Wvi  = (const float*)d_in[7];
    const float* lng  = (const float*)d_in[8];
    const float* lnb  = (const float*)d_in[9];
    const float* pw   = (const float*)d_in[10];
    const float* pb   = (const float*)d_in[11];
    const float* vis  = (const float*)d_in[12];
    const float* aud  = (const float*)d_in[13];
    const float* sw   = (const float*)d_in[14];
    const float* sb   = (const float*)d_in[15];
    const float* mk   = (const float*)d_in[16];
    const float* mv   = (const float*)d_in[17];
    const float* memw = (const float*)d_in[18];
    const float* memb = (const float*)d_in[19];
    const float* cb   = (const float*)d_in[20];
    const float* semw = (const float*)d_in[21];
    const float* semb = (const float*)d_in[22];
    const float* decW = (const float*)d_in[23];
    const float* decb = (const float*)d_in[24];
    float* out = (float*)d_out;

    cudaFuncSetAttribute(k_par, cudaFuncAttributeMaxDynamicSharedMemorySize, SMEM_MMA);
    cudaFuncSetAttribute(k_dec, cudaFuncAttributeMaxDynamicSharedMemorySize, SMEM_MMA);

    k_prep<<<NB_PREP, 256>>>(cb, decW, x, embW, mk, mv,
                             Wqr, Wqi, Wkr, Wki, Wvr, Wvi);                     // 0

    for (int t = 0; t < MAXREC; t++) {
        int off = 1536 - 128*t;
        int M   = 128 + 127*t;
        k_par<<<NB_PAR, 256, SMEM_MMA>>>(off, M, vis, aud, sw);                 // 1, 3(t=1)...
        k_row<<<Bv, 512>>>(lng, lnb, pw, pb, cb, sb, memw, memb, semw, semb, t);
    }

    k_dec<<<NPART, 256, SMEM_MMA>>>(decb, out);
    k_fin<<<1, 256>>>(out);
    (void)in_sizes; (void)n_in; (void)out_size;
}

// round 14
// speedup vs baseline: 1.1944x; 1.0453x over previous
#include <cuda_runtime.h>
#include <cuda_bf16.h>
#include <math.h>
#include <stdint.h>

#define Bv 128
#define Dv 512
#define D2 1024
#define Vv 32000
#define Av 64
#define MAXREC 12
#define KCAP 1664
#define SCALE 0.044194173824159216f
#define NPART (Vv/128)   // 250
#define NCLIN 3072

// k_par roles: mem -> VQ MMA -> clin MMA -> palette (wave-1 = mem + VQ)
#define B_VQ0  128
#define B_CLI0 378
#define B_PALX 402
#define NB_PAR 658

typedef __nv_bfloat16 bf16;

__device__ __align__(16) float g_gr[Bv*Dv], g_gi[Bv*Dv];
__device__ __align__(16) float g_qr[Bv*Dv], g_qi[Bv*Dv], g_kr[Bv*Dv], g_ki[Bv*Dv], g_vr[Bv*Dv], g_vi[Bv*Dv];
__device__ float g_ssalv[Bv], g_ssala[Bv];
__device__ __align__(16) float g_vresp[Bv*Dv], g_aresp[Bv*Dv];
__device__ __align__(16) float g_rec[Bv*Dv];
__device__ __align__(16) float g_K[KCAP*Dv], g_Vm[KCAP*Dv];
__device__ float g_kn[KCAP];
__device__ float g_grn[Bv];
__device__ float g_cn[Vv];
__device__ float g_pmin[Bv*NPART];   // [row][part] — coalesced k_row read
__device__ int   g_pidx[Bv*NPART];
__device__ float g_vqrows[MAXREC*Bv];

__device__ __align__(16) bf16 g_zh[Bv*D2], g_zl[Bv*D2];
__device__ __align__(16) bf16 g_wh[NCLIN*D2], g_wl[NCLIN*D2];
__device__ __align__(16) bf16 g_cbh[(size_t)Vv*D2], g_cbl[(size_t)Vv*D2];
__device__ __align__(16) bf16 g_dTh[(size_t)Vv*D2], g_dTl[(size_t)Vv*D2];

template<int NT>
__device__ __forceinline__ float blockSum(float v, float* sh) {
    int tid = threadIdx.x;
    #pragma unroll
    for (int o = 16; o > 0; o >>= 1) v += __shfl_down_sync(0xffffffffu, v, o);
    if ((tid & 31) == 0) sh[tid >> 5] = v;
    __syncthreads();
    float r = (tid < (NT/32)) ? sh[tid] : 0.f;
    if (tid < 32) {
        #pragma unroll
        for (int o = 16; o > 0; o >>= 1) r += __shfl_down_sync(0xffffffffu, r, o);
        if (tid == 0) sh[0] = r;
    }
    __syncthreads();
    float out = sh[0];
    __syncthreads();
    return out;
}

template<int NT>
__device__ __forceinline__ float blockMax(float v, float* sh) {
    int tid = threadIdx.x;
    #pragma unroll
    for (int o = 16; o > 0; o >>= 1) v = fmaxf(v, __shfl_down_sync(0xffffffffu, v, o));
    if ((tid & 31) == 0) sh[tid >> 5] = v;
    __syncthreads();
    float r = (tid < (NT/32)) ? sh[tid] : -3.0e38f;
    if (tid < 32) {
        #pragma unroll
        for (int o = 16; o > 0; o >>= 1) r = fmaxf(r, __shfl_down_sync(0xffffffffu, r, o));
        if (tid == 0) sh[0] = r;
    }
    __syncthreads();
    float out = sh[0];
    __syncthreads();
    return out;
}

// fused multi-value reductions for 512 threads (one barrier pair)
__device__ __forceinline__ float3 blockSum3_512(float a, float b, float c, float* sh) {
    int tid = threadIdx.x;
    #pragma unroll
    for (int o = 16; o > 0; o >>= 1) {
        a += __shfl_down_sync(0xffffffffu, a, o);
        b += __shfl_down_sync(0xffffffffu, b, o);
        c += __shfl_down_sync(0xffffffffu, c, o);
    }
    int w = tid >> 5;
    if ((tid & 31) == 0) { sh[w] = a; sh[16+w] = b; sh[32+w] = c; }
    __syncthreads();
    if (tid < 32) {
        float ra = (tid < 16) ? sh[tid]      : 0.f;
        float rb = (tid < 16) ? sh[16+tid]   : 0.f;
        float rc = (tid < 16) ? sh[32+tid]   : 0.f;
        #pragma unroll
        for (int o = 8; o > 0; o >>= 1) {
            ra += __shfl_down_sync(0xffffffffu, ra, o);
            rb += __shfl_down_sync(0xffffffffu, rb, o);
            rc += __shfl_down_sync(0xffffffffu, rc, o);
        }
        if (tid == 0) { sh[0] = ra; sh[1] = rb; sh[2] = rc; }
    }
    __syncthreads();
    float3 out = make_float3(sh[0], sh[1], sh[2]);
    __syncthreads();
    return out;
}

__device__ __forceinline__ float2 blockSum2_512(float a, float b, float* sh) {
    int tid = threadIdx.x;
    #pragma unroll
    for (int o = 16; o > 0; o >>= 1) {
        a += __shfl_down_sync(0xffffffffu, a, o);
        b += __shfl_down_sync(0xffffffffu, b, o);
    }
    int w = tid >> 5;
    if ((tid & 31) == 0) { sh[w] = a; sh[16+w] = b; }
    __syncthreads();
    if (tid < 32) {
        float ra = (tid < 16) ? sh[tid]    : 0.f;
        float rb = (tid < 16) ? sh[16+tid] : 0.f;
        #pragma unroll
        for (int o = 8; o > 0; o >>= 1) {
            ra += __shfl_down_sync(0xffffffffu, ra, o);
            rb += __shfl_down_sync(0xffffffffu, rb, o);
        }
        if (tid == 0) { sh[0] = ra; sh[1] = rb; }
    }
    __syncthreads();
    float2 out = make_float2(sh[0], sh[1]);
    __syncthreads();
    return out;
}

__device__ __forceinline__ void splitStore(float v, bf16* ph, bf16* pl) {
    bf16 h = __float2bfloat16(v);
    *ph = h;
    *pl = __float2bfloat16(v - __bfloat162float(h));
}

__device__ __forceinline__ void updMin(float v, int ix, float& bv, int& bi) {
    if (v < bv || (v == bv && ix < bi)) { bv = v; bi = ix; }
}

// ===== merged prep =====
__global__ void k_prep(const float* cb, const float* W,
                       const int* x, const float* embW, const float* mk, const float* mv,
                       const float* Wqr, const float* Wqi, const float* Wkr,
                       const float* Wki, const float* Wvr, const float* Wvi) {
    __shared__ float sh[8];
    __shared__ float tile[32][33];
    int bid = blockIdx.x, tid = threadIdx.x;
    if (bid < Vv) {
        int j = bid;
        const float* c = cb + (size_t)j * D2;
        float s = 0.f;
        for (int k = tid; k < D2; k += 256) {
            float v = c[k];
            s += v*v;
            splitStore(v, &g_cbh[(size_t)j*D2+k], &g_cbl[(size_t)j*D2+k]);
        }
        float tot = blockSum<256>(s, sh);
        if (tid == 0) g_cn[j] = tot;
    } else if (bid < 2*Vv) {
        int idx = bid - Vv;
        int n0 = (idx % 1000) * 32, k0 = (idx / 1000) * 32;
        int tx = tid & 31, ty = tid >> 5;
        for (int r = ty; r < 32; r += 8)
            tile[r][tx] = W[(size_t)(k0+r)*Vv + n0 + tx];
        __syncthreads();
        for (int r = ty; r < 32; r += 8) {
            float v = tile[tx][r];
            size_t o = (size_t)(n0+r)*D2 + k0 + tx;
            splitStore(v, &g_dTh[o], &g_dTl[o]);
        }
    } else if (bid < 2*Vv + Bv) {
        int i = bid - 2*Vv;
        const float* e = embW + (size_t)x[i] * D2;
        float sq = 0.f;
        for (int d = tid; d < Dv; d += 256) {
            float r = e[d], im = e[Dv+d];
            g_gr[i*Dv+d] = r; g_gi[i*Dv+d] = im;
            splitStore(r,  &g_zh[i*D2+d],    &g_zl[i*D2+d]);
            splitStore(im, &g_zh[i*D2+Dv+d], &g_zl[i*D2+Dv+d]);
            sq += r*r;
        }
        float tot = blockSum<256>(sq, sh);
        if (tid == 0) g_grn[i] = 1.f / fmaxf(sqrtf(tot), 1e-12f);
    } else if (bid < 2*Vv + 2*Bv) {
        int i = bid - 2*Vv - Bv;
        float s = 0.f;
        for (int d = tid; d < Dv; d += 256) {
            float k = mk[i*Dv+d];
            g_K[(1536+i)*Dv+d] = k;
            g_Vm[(1536+i)*Dv+d] = mv[i*Dv+d];
            s += k*k;
        }
        float tot = blockSum<256>(s, sh);
        if (tid == 0) g_kn[1536+i] = 1.f / fmaxf(sqrtf(tot), 1e-12f);
    } else {
        int n = (bid - 2*Vv - 2*Bv) * 2 + (tid >> 7);
        int tl = tid & 127;
        int grp = n >> 9, c = n & 511;
        const float *s1, *s2; float sg2;
        switch (grp) {
            case 0: s1=Wqr; s2=Wqi; sg2=-1.f; break;
            case 1: s1=Wqi; s2=Wqr; sg2= 1.f; break;
            case 2: s1=Wkr; s2=Wki; sg2=-1.f; break;
            case 3: s1=Wki; s2=Wkr; sg2= 1.f; break;
            case 4: s1=Wvr; s2=Wvi; sg2=-1.f; break;
            default:s1=Wvi; s2=Wvr; sg2= 1.f; break;
        }
        for (int k = tl; k < Dv; k += 128) {
            float v1 = s1[c*Dv + k];
            float v2 = sg2 * s2[c*Dv + k];
            splitStore(v1, &g_wh[n*D2+k],    &g_wl[n*D2+k]);
            splitStore(v2, &g_wh[n*D2+Dv+k], &g_wl[n*D2+Dv+k]);
        }
    }
}
#define NB_PREP (2*Vv + 2*Bv + NCLIN/2)

#define MMA16816(c, a, b) \
    asm volatile("mma.sync.aligned.m16n8k16.row.col.f32.bf16.bf16.f32 " \
        "{%0,%1,%2,%3},{%4,%5,%6,%7},{%8,%9},{%0,%1,%2,%3};" \
        : "+f"(c[0]), "+f"(c[1]), "+f"(c[2]), "+f"(c[3]) \
        : "r"(a[0]), "r"(a[1]), "r"(a[2]), "r"(a[3]), "r"(b[0]), "r"(b[1]))

#define LDSM4(d0, d1, d2, d3, addr) \
    asm volatile("ldmatrix.sync.aligned.m8n8.x4.shared.b16 {%0,%1,%2,%3}, [%4];" \
        : "=r"(d0), "=r"(d1), "=r"(d2), "=r"(d3) : "r"(addr))

#define CPA16(dst, src) \
    asm volatile("cp.async.cg.shared.global [%0], [%1], 16;" :: "r"(dst), "l"(src))

#define TP 40
#define SARR (128*TP*2)
#define SSTG (4*SARR)
#define SMEM_MMA (2*SSTG)

template<bool VQMODE>
__device__ __forceinline__ void mma_tile(char* dsm, int n0,
                                         const bf16* __restrict__ Bhp,
                                         const bf16* __restrict__ Blp, int pbid) {
    const uint32_t sb = (uint32_t)__cvta_generic_to_shared(dsm);
    const int tid = threadIdx.x;
    const int wid = tid >> 5, lane = tid & 31;
    const int wm = wid >> 2, wn = wid & 3;
    const int g = lane >> 2, tig = lane & 3;
    const int tg = lane >> 3, tr = lane & 7;
    const int a_row = ((tg & 1) << 3) + tr;
    const int a_col = (tg >> 1) << 3;
    const int b_row = ((tg >> 1) << 3) + tr;
    const int b_col = (tg & 1) << 3;

    float acc[4][4][4];
    #pragma unroll
    for (int a = 0; a < 4; a++)
        #pragma unroll
        for (int b = 0; b < 4; b++)
            #pragma unroll
            for (int c = 0; c < 4; c++) acc[a][b][c] = 0.f;

    const int zr0 = tid >> 2,         zs0 = (tid & 3) * 8;
    const int zr1 = (tid + 256) >> 2, zs1 = ((tid + 256) & 3) * 8;

    auto loadStage = [&](int stg, int k0) {
        uint32_t s0 = sb + stg * SSTG;
        CPA16(s0 +            (zr0*TP + zs0)*2, &g_zh[(size_t)zr0*D2 + k0 + zs0]);
        CPA16(s0 +            (zr1*TP + zs1)*2, &g_zh[(size_t)zr1*D2 + k0 + zs1]);
        CPA16(s0 +   SARR +   (zr0*TP + zs0)*2, &g_zl[(size_t)zr0*D2 + k0 + zs0]);
        CPA16(s0 +   SARR +   (zr1*TP + zs1)*2, &g_zl[(size_t)zr1*D2 + k0 + zs1]);
        CPA16(s0 + 2*SARR +   (zr0*TP + zs0)*2, &Bhp[(size_t)(n0+zr0)*D2 + k0 + zs0]);
        CPA16(s0 + 2*SARR +   (zr1*TP + zs1)*2, &Bhp[(size_t)(n0+zr1)*D2 + k0 + zs1]);
        CPA16(s0 + 3*SARR +   (zr0*TP + zs0)*2, &Blp[(size_t)(n0+zr0)*D2 + k0 + zs0]);
        CPA16(s0 + 3*SARR +   (zr1*TP + zs1)*2, &Blp[(size_t)(n0+zr1)*D2 + k0 + zs1]);
        asm volatile("cp.async.commit_group;");
    };

    loadStage(0, 0);

    const int NKC = D2 / 32;
    for (int kc = 0; kc < NKC; kc++) {
        if (kc + 1 < NKC) {
            loadStage((kc + 1) & 1, (kc + 1) * 32);
            asm volatile("cp.async.wait_group 1;");
        } else {
            asm volatile("cp.async.wait_group 0;");
        }
        __syncthreads();

        const uint32_t s0 = sb + (kc & 1) * SSTG;
        #pragma unroll
        for (int sub = 0; sub < 2; sub++) {
            const int kb = sub * 16;
            uint32_t af[4][4], bh2[4][2], bl2[4][2];
            #pragma unroll
            for (int fm = 0; fm < 4; fm++) {
                uint32_t addr = s0 + ((wm*64 + fm*16 + a_row)*TP + kb + a_col)*2;
                LDSM4(af[fm][0], af[fm][1], af[fm][2], af[fm][3], addr);
            }
            #pragma unroll
            for (int p = 0; p < 2; p++) {
                uint32_t addr = s0 + 2*SARR + ((wn*32 + p*16 + b_row)*TP + kb + b_col)*2;
                LDSM4(bh2[2*p][0], bh2[2*p][1], bh2[2*p+1][0], bh2[2*p+1][1], addr);
            }
            #pragma unroll
            for (int fm = 0; fm < 4; fm++)
                #pragma unroll
                for (int fn = 0; fn < 4; fn++) MMA16816(acc[fm][fn], af[fm], bh2[fn]);
            #pragma unroll
            for (int p = 0; p < 2; p++) {
                uint32_t addr = s0 + 3*SARR + ((wn*32 + p*16 + b_row)*TP + kb + b_col)*2;
                LDSM4(bl2[2*p][0], bl2[2*p][1], bl2[2*p+1][0], bl2[2*p+1][1], addr);
            }
            #pragma unroll
            for (int fm = 0; fm < 4; fm++)
                #pragma unroll
                for (int fn = 0; fn < 4; fn++) MMA16816(acc[fm][fn], af[fm], bl2[fn]);
            #pragma unroll
            for (int fm = 0; fm < 4; fm++) {
                uint32_t addr = s0 + SARR + ((wm*64 + fm*16 + a_row)*TP + kb + a_col)*2;
                LDSM4(af[fm][0], af[fm][1], af[fm][2], af[fm][3], addr);
            }
            #pragma unroll
            for (int fm = 0; fm < 4; fm++)
                #pragma unroll
                for (int fn = 0; fn < 4; fn++) MMA16816(acc[fm][fn], af[fm], bh2[fn]);
        }
        __syncthreads();
    }

    if (!VQMODE) {
        float* outs[6] = {g_qr, g_qi, g_kr, g_ki, g_vr, g_vi};
        #pragma unroll
        for (int fm = 0; fm < 4; fm++) {
            int r = wm*64 + fm*16 + g;
            #pragma unroll
            for (int fn = 0; fn < 4; fn++) {
                int gcol = n0 + wn*32 + fn*8 + tig*2;
                float* dst = outs[gcol >> 9];
                int c = gcol & 511;
                *(float2*)&dst[r*Dv + c]     = make_float2(acc[fm][fn][0], acc[fm][fn][1]);
                *(float2*)&dst[(r+8)*Dv + c] = make_float2(acc[fm][fn][2], acc[fm][fn][3]);
            }
        }
    } else {
        float* minv = (float*)dsm;
        int*   mini = (int*)(dsm + 128*4*sizeof(float));
        #pragma unroll
        for (int fm = 0; fm < 4; fm++) {
            int r0 = wm*64 + fm*16 + g;
            float bv0 = 3.0e38f, bv1 = 3.0e38f;
            int bi0 = 0x7fffffff, bi1 = 0x7fffffff;
            #pragma unroll
            for (int fn = 0; fn < 4; fn++) {
                int gcol = n0 + wn*32 + fn*8 + tig*2;
                float cn0 = g_cn[gcol], cn1 = g_cn[gcol+1];
                updMin(cn0 - 2.f*acc[fm][fn][0], gcol,   bv0, bi0);
                updMin(cn1 - 2.f*acc[fm][fn][1], gcol+1, bv0, bi0);
                updMin(cn0 - 2.f*acc[fm][fn][2], gcol,   bv1, bi1);
                updMin(cn1 - 2.f*acc[fm][fn][3], gcol+1, bv1, bi1);
            }
            #pragma unroll
            for (int o = 1; o <= 2; o <<= 1) {
                float ov = __shfl_xor_sync(0xffffffffu, bv0, o);
                int   oi = __shfl_xor_sync(0xffffffffu, bi0, o);
                updMin(ov, oi, bv0, bi0);
                ov = __shfl_xor_sync(0xffffffffu, bv1, o);
                oi = __shfl_xor_sync(0xffffffffu, bi1, o);
                updMin(ov, oi, bv1, bi1);
            }
            if (tig == 0) {
                minv[r0*4 + wn] = bv0; mini[r0*4 + wn] = bi0;
                minv[(r0+8)*4 + wn] = bv1; mini[(r0+8)*4 + wn] = bi1;
            }
        }
        __syncthreads();
        if (tid < 128) {
            float bv = 3.0e38f; int bi = 0x7fffffff;
            #pragma unroll
            for (int w = 0; w < 4; w++) updMin(minv[tid*4+w], mini[tid*4+w], bv, bi);
            g_pmin[tid*NPART + pbid] = bv;   // transposed: [row][part]
            g_pidx[tid*NPART + pbid] = bi;
        }
    }
}

// ===== fused parallel kernel: mem, VQ, clin, palette =====
__global__ __launch_bounds__(256, 2) void k_par(int off, int M,
                                                const float* __restrict__ vis,
                                                const float* __restrict__ aud,
                                                const float* __restrict__ sw) {
    extern __shared__ __align__(16) char dsm[];
    int bid = blockIdx.x, tid = threadIdx.x;

    if (bid < B_VQ0) {
        // ---- memory attention + fused push ----
        float* mg  = (float*)dsm;
        float* mlg = mg + 512;
        float* msh = mlg + 1536;
        int i = bid;
        for (int k = tid; k < Dv; k += 256) mg[k] = g_gr[i*Dv+k];
        __syncthreads();
        float rni = g_grn[i];
        float lmax = -3.0e38f;
        for (int m = tid; m < M; m += 256) {
            const float* kp = &g_K[(size_t)(off+m)*Dv];
            float s0 = 0.f, s1 = 0.f, s2 = 0.f, s3 = 0.f;
            for (int k = 0; k < Dv; k += 16) {
                float4 a = *(const float4*)&kp[k];
                float4 b = *(const float4*)&kp[k+4];
                float4 c = *(const float4*)&kp[k+8];
                float4 d = *(const float4*)&kp[k+12];
                s0 += mg[k]*a.x + mg[k+1]*a.y + mg[k+2]*a.z + mg[k+3]*a.w;
                s1 += mg[k+4]*b.x + mg[k+5]*b.y + mg[k+6]*b.z + mg[k+7]*b.w;
                s2 += mg[k+8]*c.x + mg[k+9]*c.y + mg[k+10]*c.z + mg[k+11]*c.w;
                s3 += mg[k+12]*d.x + mg[k+13]*d.y + mg[k+14]*d.z + mg[k+15]*d.w;
            }
            float l = 5.f * ((s0+s1)+(s2+s3)) * rni * g_kn[off+m];
            mlg[m] = l;
            lmax = fmaxf(lmax, l);
        }
        float mx = blockMax<256>(lmax, msh);
        float lsum = 0.f;
        for (int m = tid; m < M; m += 256) { float e = expf(mlg[m]-mx); mlg[m] = e; lsum += e; }
        float sum = blockSum<256>(lsum, msh);
        float inv = 1.f / sum;
        float a00 = 0.f, a01 = 0.f, a10 = 0.f, a11 = 0.f;
        int m = 0;
        for (; m + 1 < M; m += 2) {
            float w0 = mlg[m], w1 = mlg[m+1];
            const float* vp0 = &g_Vm[(size_t)(off+m)*Dv];
            const float* vp1 = vp0 + Dv;
            a00 += w0 * vp0[tid]; a01 += w0 * vp0[tid+256];
            a10 += w1 * vp1[tid]; a11 += w1 * vp1[tid+256];
        }
        if (m < M) {
            float w0 = mlg[m];
            const float* vp0 = &g_Vm[(size_t)(off+m)*Dv];
            a00 += w0 * vp0[tid]; a01 += w0 * vp0[tid+256];
        }
        g_rec[i*Dv + tid]       = (a00 + a10) * inv;
        g_rec[i*Dv + tid + 256] = (a01 + a11) * inv;
        {
            int noff = off - 128;
            float v0 = mg[tid], v1 = mg[tid + 256];
            g_K [(size_t)(noff+i)*Dv + tid]       = v0;
            g_K [(size_t)(noff+i)*Dv + tid + 256] = v1;
            g_Vm[(size_t)(noff+i)*Dv + tid]       = v0;
            g_Vm[(size_t)(noff+i)*Dv + tid + 256] = v1;
            if (tid == 0) g_kn[noff+i] = rni;
        }
    } else if (bid < B_CLI0) {
        mma_tile<true>(dsm, (bid - B_VQ0) * 128, g_cbh, g_cbl, bid - B_VQ0);
    } else if (bid < B_PALX) {
        mma_tile<false>(dsm, (bid - B_CLI0) * 128, g_wh, g_wl, 0);
    } else {
        // ---- palette ----
        float* pg  = (float*)dsm;
        float* plg = pg + 512;
        float* psh = plg + 64;
        int r = bid - B_PALX;
        int i = r >> 1, z = r & 1;
        const float* src = z ? g_gi : g_gr;
        const float* P   = z ? aud : vis;
        float* resp      = z ? g_aresp : g_vresp;
        const float* swp = sw + z*Dv;
        for (int k = tid; k < Dv; k += 256) pg[k] = src[i*Dv+k];
        __syncthreads();
        {
            int a = tid >> 2, part = tid & 3;
            float s = 0.f;
            const float* pr = &P[a*Dv + part*128];
            const float* gq = &pg[part*128];
            for (int k = 0; k < 128; k += 4) {
                float4 p4 = *(const float4*)&pr[k];
                s += gq[k]*p4.x + gq[k+1]*p4.y + gq[k+2]*p4.z + gq[k+3]*p4.w;
            }
            s += __shfl_xor_sync(0xffffffffu, s, 1);
            s += __shfl_xor_sync(0xffffffffu, s, 2);
            if (part == 0) plg[a] = s;
        }
        __syncthreads();
        if (tid == 0) {
            float mx = -3.0e38f;
            for (int a = 0; a < Av; a++) mx = fmaxf(mx, plg[a]);
            float su = 0.f;
            for (int a = 0; a < Av; a++) { float e = expf(plg[a]-mx); plg[a] = e; su += e; }
            float inv = 1.f/su;
            for (int a = 0; a < Av; a++) plg[a] *= inv;
        }
        __syncthreads();
        float sal = 0.f;
        for (int d = tid; d < Dv; d += 256) {
            float acc = 0.f;
            for (int a = 0; a < Av; a++) acc += plg[a] * P[a*Dv + d];
            resp[i*Dv + d] = acc;
            sal += acc * swp[d];
        }
        float st = blockSum<256>(sal, psh);
        if (tid == 0) { if (z) g_ssala[i] = st; else g_ssalv[i] = st; }
    }
}

__global__ __launch_bounds__(256, 2) void k_dec(const float* __restrict__ bias,
                                                float* __restrict__ out) {
    extern __shared__ __align__(16) char dsm[];
    const uint32_t sb = (uint32_t)__cvta_generic_to_shared(dsm);
    const int tid = threadIdx.x;
    const int wid = tid >> 5, lane = tid & 31;
    const int wm = wid >> 2, wn = wid & 3;
    const int g = lane >> 2, tig = lane & 3;
    const int n0 = blockIdx.x * 128;
    const int tg = lane >> 3, tr = lane & 7;
    const int a_row = ((tg & 1) << 3) + tr;
    const int a_col = (tg >> 1) << 3;
    const int b_row = ((tg >> 1) << 3) + tr;
    const int b_col = (tg & 1) << 3;

    float acc[4][4][4];
    #pragma unroll
    for (int a = 0; a < 4; a++)
        #pragma unroll
        for (int b = 0; b < 4; b++)
            #pragma unroll
            for (int c = 0; c < 4; c++) acc[a][b][c] = 0.f;

    const int zr0 = tid >> 2,         zs0 = (tid & 3) * 8;
    const int zr1 = (tid + 256) >> 2, zs1 = ((tid + 256) & 3) * 8;

    auto loadStage = [&](int stg, int k0) {
        uint32_t s0 = sb + stg * SSTG;
        CPA16(s0 +            (zr0*TP + zs0)*2, &g_zh[(size_t)zr0*D2 + k0 + zs0]);
        CPA16(s0 +            (zr1*TP + zs1)*2, &g_zh[(size_t)zr1*D2 + k0 + zs1]);
        CPA16(s0 +   SARR +   (zr0*TP + zs0)*2, &g_zl[(size_t)zr0*D2 + k0 + zs0]);
        CPA16(s0 +   SARR +   (zr1*TP + zs1)*2, &g_zl[(size_t)zr1*D2 + k0 + zs1]);
        CPA16(s0 + 2*SARR +   (zr0*TP + zs0)*2, &g_dTh[(size_t)(n0+zr0)*D2 + k0 + zs0]);
        CPA16(s0 + 2*SARR +   (zr1*TP + zs1)*2, &g_dTh[(size_t)(n0+zr1)*D2 + k0 + zs1]);
        CPA16(s0 + 3*SARR +   (zr0*TP + zs0)*2, &g_dTl[(size_t)(n0+zr0)*D2 + k0 + zs0]);
        CPA16(s0 + 3*SARR +   (zr1*TP + zs1)*2, &g_dTl[(size_t)(n0+zr1)*D2 + k0 + zs1]);
        asm volatile("cp.async.commit_group;");
    };

    loadStage(0, 0);
    const int NKC = D2 / 32;
    for (int kc = 0; kc < NKC; kc++) {
        if (kc + 1 < NKC) {
            loadStage((kc + 1) & 1, (kc + 1) * 32);
            asm volatile("cp.async.wait_group 1;");
        } else {
            asm volatile("cp.async.wait_group 0;");
        }
        __syncthreads();
        const uint32_t s0 = sb + (kc & 1) * SSTG;
        #pragma unroll
        for (int sub = 0; sub < 2; sub++) {
            const int kb = sub * 16;
            uint32_t af[4][4], bh2[4][2], bl2[4][2];
            #pragma unroll
            for (int fm = 0; fm < 4; fm++) {
                uint32_t addr = s0 + ((wm*64 + fm*16 + a_row)*TP + kb + a_col)*2;
                LDSM4(af[fm][0], af[fm][1], af[fm][2], af[fm][3], addr);
            }
            #pragma unroll
            for (int p = 0; p < 2; p++) {
                uint32_t addr = s0 + 2*SARR + ((wn*32 + p*16 + b_row)*TP + kb + b_col)*2;
                LDSM4(bh2[2*p][0], bh2[2*p][1], bh2[2*p+1][0], bh2[2*p+1][1], addr);
            }
            #pragma unroll
            for (int fm = 0; fm < 4; fm++)
                #pragma unroll
                for (int fn = 0; fn < 4; fn++) MMA16816(acc[fm][fn], af[fm], bh2[fn]);
            #pragma unroll
            for (int p = 0; p < 2; p++) {
                uint32_t addr = s0 + 3*SARR + ((wn*32 + p*16 + b_row)*TP + kb + b_col)*2;
                LDSM4(bl2[2*p][0], bl2[2*p][1], bl2[2*p+1][0], bl2[2*p+1][1], addr);
            }
            #pragma unroll
            for (int fm = 0; fm < 4; fm++)
                #pragma unroll
                for (int fn = 0; fn < 4; fn++) MMA16816(acc[fm][fn], af[fm], bl2[fn]);
            #pragma unroll
            for (int fm = 0; fm < 4; fm++) {
                uint32_t addr = s0 + SARR + ((wm*64 + fm*16 + a_row)*TP + kb + a_col)*2;
                LDSM4(af[fm][0], af[fm][1], af[fm][2], af[fm][3], addr);
            }
            #pragma unroll
            for (int fm = 0; fm < 4; fm++)
                #pragma unroll
                for (int fn = 0; fn < 4; fn++) MMA16816(acc[fm][fn], af[fm], bh2[fn]);
        }
        __syncthreads();
    }
    #pragma unroll
    for (int fm = 0; fm < 4; fm++) {
        int r = wm*64 + fm*16 + g;
        #pragma unroll
        for (int fn = 0; fn < 4; fn++) {
            int gcol = n0 + wn*32 + fn*8 + tig*2;
            float b0 = bias[gcol], b1 = bias[gcol+1];
            *(float2*)&out[(size_t)r*Vv + gcol] =
                make_float2(acc[fm][fn][0] + b0, acc[fm][fn][1] + b1);
            *(float2*)&out[(size_t)(r+8)*Vv + gcol] =
                make_float2(acc[fm][fn][2] + b0, acc[fm][fn][3] + b1);
        }
    }
}

// ===== fused per-row kernel, 512 threads =====
__global__ __launch_bounds__(512) void k_row(const float* lng, const float* lnb,
        const float* pw, const float* pb, const float* cb, const float* sensb,
        const float* memw, const float* memb, const float* semw, const float* semb, int t) {
    __shared__ float q[D2];
    __shared__ float part[4][Bv];
    __shared__ float att[Bv];
    __shared__ float sh[48];
    __shared__ float w[4];
    __shared__ float sv[512]; __shared__ int si[512];
    __shared__ int sidx;
    int i = blockIdx.x, tid = threadIdx.x;

    {
        float bv = 3.0e38f; int bi = 0x7fffffff;
        if (tid < NPART) { bv = g_pmin[i*NPART + tid]; bi = g_pidx[i*NPART + tid]; }  // coalesced
        sv[tid] = bv; si[tid] = bi;
    }
    q[tid]      = g_qr[i*Dv + tid];
    q[Dv + tid] = g_qi[i*Dv + tid];
    __syncthreads();
    // tree to 32, then warp shuffle
    #pragma unroll
    for (int s = 256; s >= 32; s >>= 1) {
        if (tid < s) {
            float v = sv[tid+s]; int ix = si[tid+s];
            if (v < sv[tid] || (v == sv[tid] && ix < si[tid])) { sv[tid] = v; si[tid] = ix; }
        }
        __syncthreads();
    }
    if (tid < 32) {
        float bv = sv[tid]; int bi = si[tid];
        #pragma unroll
        for (int o = 16; o > 0; o >>= 1) {
            float ov = __shfl_down_sync(0xffffffffu, bv, o);
            int   oi = __shfl_down_sync(0xffffffffu, bi, o);
            updMin(ov, oi, bv, bi);
        }
        if (tid == 0) sidx = bi;
    }
    __syncthreads();
    const float* c = &cb[(size_t)sidx*D2];

    {
        int j = tid & 127, seg = tid >> 7;
        const float* kv = (seg < 2) ? &g_kr[j*Dv + (seg & 1)*256]
                                    : &g_ki[j*Dv + (seg & 1)*256];
        const float* qv = &q[seg*256];
        float s0 = 0.f, s1 = 0.f;
        for (int k = 0; k < 256; k += 8) {
            float4 a = *(const float4*)&kv[k];
            float4 a2 = *(const float4*)&kv[k+4];
            s0 += qv[k]*a.x + qv[k+1]*a.y + qv[k+2]*a.z + qv[k+3]*a.w;
            s1 += qv[k+4]*a2.x + qv[k+5]*a2.y + qv[k+6]*a2.z + qv[k+7]*a2.w;
        }
        part[seg][j] = s0 + s1;
    }
    __syncthreads();
    float logit = (tid < 128)
        ? (part[0][tid] + part[1][tid] + part[2][tid] + part[3][tid]) * SCALE
        : -3.0e38f;
    float mx = blockMax<512>(logit, sh);
    float e = (tid < 128) ? expf(logit - mx) : 0.f;
    float es = blockSum<512>(e, sh);
    if (tid < 128) att[tid] = e / es;
    __syncthreads();

    float fr = 0.f, fi = 0.f;
    {
        const float* vr = &g_vr[tid];
        const float* vi = &g_vi[tid];
        for (int j = 0; j + 4 <= Bv; j += 4) {
            float w0 = att[j], w1 = att[j+1], w2 = att[j+2], w3 = att[j+3];
            fr += w0*vr[(j)*Dv] + w1*vr[(j+1)*Dv] + w2*vr[(j+2)*Dv] + w3*vr[(j+3)*Dv];
            fi += w0*vi[(j)*Dv] + w1*vi[(j+1)*Dv] + w2*vi[(j+2)*Dv] + w3*vi[(j+3)*Dv];
        }
    }
    float m = blockSum<512>(fr + fi, sh) * (1.f/1024.f);
    float d0 = fr - m, d1 = fi - m;
    float var = blockSum<512>(d0*d0 + d1*d1, sh) * (1.f/1024.f);
    float rstd = rsqrtf(var + 1e-5f);
    int c0 = tid, c2 = Dv + tid;
    float yr = d0*rstd*lng[c0] + lnb[c0];
    float yi = d1*rstd*lng[c2] + lnb[c2];
    float recv = g_rec[i*Dv + tid];
    // fused triple reduction: psal / md / sd
    float3 r3 = blockSum3_512(yr*pw[c0] + yi*pw[c2],
                              recv * memw[tid],
                              c[c0]*semw[c0] + c[c2]*semw[c2], sh);
    if (tid == 0) {
        float a0 = (r3.x + pb[0]) * 1.25f;
        float a1 = (g_ssalv[i] + g_ssala[i] + sensb[0]) * 1.25f;
        float a2 = (r3.y + memb[0]) * 1.25f;
        float a3 = (r3.z + semb[0]) * 1.25f;
        float mxx = fmaxf(fmaxf(a0,a1), fmaxf(a2,a3));
        float e0 = expf(a0-mxx), e1 = expf(a1-mxx), e2 = expf(a2-mxx), e3 = expf(a3-mxx);
        float inv = 1.f / (e0+e1+e2+e3);
        w[0]=e0*inv; w[1]=e1*inv; w[2]=e2*inv; w[3]=e3*inv;
    }
    __syncthreads();
    float w0 = w[0], w1 = w[1], w2 = w[2], w3 = w[3];
    int d = tid;
    float ogr = g_gr[i*Dv+d], ogi = g_gi[i*Dv+d];
    float cr = c[d], ci = c[Dv+d];
    float dr = cr-ogr, di = ci-ogi;
    float vql = dr*dr + di*di;
    float nr = w0*yr + w1*g_vresp[i*Dv+d] + w2*recv + w3*cr;
    float ni = w0*yi + w1*g_aresp[i*Dv+d]           + w3*ci;
    float ngr = 0.6f*ogr + 0.4f*nr, ngi = 0.6f*ogi + 0.4f*ni;
    g_gr[i*Dv+d] = ngr; g_gi[i*Dv+d] = ngi;
    splitStore(ngr, &g_zh[i*D2+d],    &g_zl[i*D2+d]);
    splitStore(ngi, &g_zh[i*D2+Dv+d], &g_zl[i*D2+Dv+d]);
    float2 r2 = blockSum2_512(ngr*ngr, vql, sh);
    if (tid == 0) {
        g_grn[i] = 1.f / fmaxf(sqrtf(r2.x), 1e-12f);
        g_vqrows[t*Bv + i] = r2.y;
    }
}

__global__ void k_fin(float* out) {
    __shared__ float sh[8];
    int tid = threadIdx.x;
    float s = 0.f;
    for (int k = tid; k < MAXREC*Bv; k += 256) s += g_vqrows[k];
    float tot = blockSum<256>(s, sh);
    if (tid == 0) {
        out[(size_t)Bv*Vv]     = 1.25f * tot / 131072.f;
        out[(size_t)Bv*Vv + 1] = (float)MAXREC;
    }
}

extern "C" void kernel_launch(void* const* d_in, const int* in_sizes, int n_in,
                              void* d_out, int out_size) {
    const int*   x    = (const int*)d_in[0];
    const float* embW = (const float*)d_in[1];
    const float* Wqr  = (const float*)d_in[2];
    const float* Wqi  = (const float*)d_in[3];
    const float* Wkr  = (const float*)d_in[4];
    const float* Wki  = (const float*)d_in[5];
    const float* Wvr  = (const float*)d_in[6];
    const float* Wvi  = (const float*)d_in[7];
    const float* lng  = (const float*)d_in[8];
    const float* lnb  = (const float*)d_in[9];
    const float* pw   = (const float*)d_in[10];
    const float* pb   = (const float*)d_in[11];
    const float* vis  = (const float*)d_in[12];
    const float* aud  = (const float*)d_in[13];
    const float* sw   = (const float*)d_in[14];
    const float* sb   = (const float*)d_in[15];
    const float* mk   = (const float*)d_in[16];
    const float* mv   = (const float*)d_in[17];
    const float* memw = (const float*)d_in[18];
    const float* memb = (const float*)d_in[19];
    const float* cb   = (const float*)d_in[20];
    const float* semw = (const float*)d_in[21];
    const float* semb = (const float*)d_in[22];
    const float* decW = (const float*)d_in[23];
    const float* decb = (const float*)d_in[24];
    float* out = (float*)d_out;

    cudaFuncSetAttribute(k_par, cudaFuncAttributeMaxDynamicSharedMemorySize, SMEM_MMA);
    cudaFuncSetAttribute(k_dec, cudaFuncAttributeMaxDynamicSharedMemorySize, SMEM_MMA);

    k_prep<<<NB_PREP, 256>>>(cb, decW, x, embW, mk, mv,
                             Wqr, Wqi, Wkr, Wki, Wvr, Wvi);                     // 0

    for (int t = 0; t < MAXREC; t++) {
        int off = 1536 - 128*t;
        int M   = 128 + 127*t;
        k_par<<<NB_PAR, 256, SMEM_MMA>>>(off, M, vis, aud, sw);                 // 1, 3(t=1)...
        k_row<<<Bv, 512>>>(lng, lnb, pw, pb, cb, sb, memw, memb, semw, semb, t);
    }

    k_dec<<<NPART, 256, SMEM_MMA>>>(decb, out);
    k_fin<<<1, 256>>>(out);
    (void)in_sizes; (void)n_in; (void)out_size;
}